// round 4
// baseline (speedup 1.0000x reference)
#include <cuda_runtime.h>
#include <math.h>

// ---------------- problem constants ----------------
#define Bn   2
#define Sn   2048
#define En   1024
#define Hn   1344
#define H2n  2688
#define NHn  4
#define DHn  336
#define TOT  (Bn*Sn)          // 4096 rows

// ---------------- device scratch (no allocs allowed) ----------------
__device__ float g_xinner[TOT * H2n];  // up-proj output: [x_m | z]
__device__ float g_act   [TOT * Hn];   // silu(conv(x_m))
__device__ float g_q     [TOT * Hn];
__device__ float g_k     [TOT * Hn];
__device__ float g_v     [TOT * Hn];
__device__ float g_h     [TOT * Hn];   // mLSTM cell output (B,S,H layout)
__device__ float g_hst   [TOT * Hn];   // post-LN/skip/gate
__device__ float g_ig    [Bn*NHn*Sn];
__device__ float g_lf    [Bn*NHn*Sn];  // logsigmoid(fg)
__device__ float g_a     [Bn*NHn*Sn];  // a_t = ig_t - c_t
__device__ float g_M     [Bn*NHn*Sn];  // running max of a
__device__ float g_nfl   [Bn*NHn*Sn];  // exp(-m_s)

// ---------------- generic fp32 tiled GEMM: C = A(MxK) * B(KxN) ----------------
// BM=64, BN=64, BK=16, 256 threads, 4x4 micro-tile per thread.
// Requires M%64==0, N%64==0, K%16==0 (holds for all our shapes).
__global__ void sgemm_kernel(const float* __restrict__ A,
                             const float* __restrict__ B,
                             float* __restrict__ C,
                             int M, int N, int Kd) {
    const int BM = 64, BN = 64, BK = 16, TM = 4, TN = 4;
    __shared__ float As[BK][BM];
    __shared__ float Bs[BK][BN];
    int bx = blockIdx.x;              // N tile
    int by = blockIdx.y;              // M tile
    int tid = threadIdx.x;            // 0..255
    int tx = tid % (BN / TN);         // 0..15
    int ty = tid / (BN / TN);         // 0..15

    float acc[TM][TN];
    #pragma unroll
    for (int i = 0; i < TM; i++)
        #pragma unroll
        for (int j = 0; j < TN; j++) acc[i][j] = 0.f;

    for (int k0 = 0; k0 < Kd; k0 += BK) {
        // load A tile (BM x BK) transposed into As[BK][BM]
        #pragma unroll
        for (int i = tid; i < BM * BK; i += 256) {
            int r = i / BK, c = i % BK;
            As[c][r] = A[(by * BM + r) * Kd + k0 + c];
        }
        // load B tile (BK x BN)
        #pragma unroll
        for (int i = tid; i < BK * BN; i += 256) {
            int r = i / BN, c = i % BN;
            Bs[r][c] = B[(k0 + r) * N + bx * BN + c];
        }
        __syncthreads();
        #pragma unroll
        for (int kk = 0; kk < BK; kk++) {
            float av[TM], bv[TN];
            #pragma unroll
            for (int i = 0; i < TM; i++) av[i] = As[kk][ty * TM + i];
            #pragma unroll
            for (int j = 0; j < TN; j++) bv[j] = Bs[kk][tx * TN + j];
            #pragma unroll
            for (int i = 0; i < TM; i++)
                #pragma unroll
                for (int j = 0; j < TN; j++) acc[i][j] += av[i] * bv[j];
        }
        __syncthreads();
    }
    #pragma unroll
    for (int i = 0; i < TM; i++)
        #pragma unroll
        for (int j = 0; j < TN; j++)
            C[(by * BM + ty * TM + i) * N + bx * BN + tx * TN + j] = acc[i][j];
}

// ---------------- causal depthwise conv (K=4) + bias + SiLU ----------------
__global__ void conv_silu_kernel(const float* __restrict__ conv_k,
                                 const float* __restrict__ conv_b) {
    int idx = blockIdx.x * blockDim.x + threadIdx.x;
    if (idx >= TOT * Hn) return;
    int h = idx % Hn;
    int p = idx / Hn;          // b*S + s
    int s = p % Sn;
    float acc = conv_b[h];
    #pragma unroll
    for (int j = 0; j < 4; j++) {
        int t = s - 3 + j;
        if (t >= 0) acc += g_xinner[(p - s + t) * H2n + h] * conv_k[j * Hn + h];
    }
    float sg = 1.f / (1.f + expf(-acc));
    g_act[idx] = acc * sg;
}

// ---------------- headwise 4x4 block-diagonal projections ----------------
__global__ void headwise_kernel(const float* __restrict__ Wq,
                                const float* __restrict__ Wk,
                                const float* __restrict__ Wv) {
    int idx = blockIdx.x * blockDim.x + threadIdx.x;
    if (idx >= TOT * Hn) return;
    int h = idx % Hn;
    int p = idx / Hn;
    int head = h >> 2;
    int o = h & 3;
    const float* a  = &g_act[p * Hn + head * 4];
    const float* xm = &g_xinner[p * H2n + head * 4];
    float q = 0.f, k = 0.f, v = 0.f;
    #pragma unroll
    for (int d = 0; d < 4; d++) {
        float wq = Wq[head * 16 + d * 4 + o];
        float wk = Wk[head * 16 + d * 4 + o];
        float wv = Wv[head * 16 + d * 4 + o];
        q += a[d] * wq;
        k += a[d] * wk;
        v += xm[d] * wv;
    }
    g_q[idx] = q; g_k[idx] = k; g_v[idx] = v;
}

// ---------------- input/forget gate projections ----------------
// one block per (b,s): gin = [q;k;v] (3H) dot W_ig/W_fg columns (NH=4 each)
__global__ void gates_kernel(const float* __restrict__ W_ig,
                             const float* __restrict__ b_ig,
                             const float* __restrict__ W_fg,
                             const float* __restrict__ b_fg) {
    int p = blockIdx.x;          // 0..TOT-1
    int tid = threadIdx.x;       // 128
    float aig[4] = {0, 0, 0, 0}, afg[4] = {0, 0, 0, 0};
    const float4* wig4 = (const float4*)W_ig;
    const float4* wfg4 = (const float4*)W_fg;
    for (int i = tid; i < 3 * Hn; i += 128) {
        float g;
        if (i < Hn)            g = g_q[p * Hn + i];
        else if (i < 2 * Hn)   g = g_k[p * Hn + i - Hn];
        else                   g = g_v[p * Hn + i - 2 * Hn];
        float4 wi = wig4[i];
        float4 wf = wfg4[i];
        aig[0] += g * wi.x; aig[1] += g * wi.y; aig[2] += g * wi.z; aig[3] += g * wi.w;
        afg[0] += g * wf.x; afg[1] += g * wf.y; afg[2] += g * wf.z; afg[3] += g * wf.w;
    }
    __shared__ float sred[4];
    float rig[4], rfg[4];
    #pragma unroll
    for (int n = 0; n < 4; n++) {
        float v = aig[n];
        #pragma unroll
        for (int o = 16; o > 0; o >>= 1) v += __shfl_down_sync(0xffffffffu, v, o);
        if ((tid & 31) == 0) sred[tid >> 5] = v;
        __syncthreads();
        if (tid == 0) rig[n] = sred[0] + sred[1] + sred[2] + sred[3];
        __syncthreads();
        v = afg[n];
        #pragma unroll
        for (int o = 16; o > 0; o >>= 1) v += __shfl_down_sync(0xffffffffu, v, o);
        if ((tid & 31) == 0) sred[tid >> 5] = v;
        __syncthreads();
        if (tid == 0) rfg[n] = sred[0] + sred[1] + sred[2] + sred[3];
        __syncthreads();
    }
    if (tid == 0) {
        int b = p / Sn, s = p % Sn;
        #pragma unroll
        for (int n = 0; n < 4; n++) {
            float igv = rig[n] + b_ig[n];
            float fgv = rfg[n] + b_fg[n];
            int o = (b * NHn + n) * Sn + s;
            g_ig[o] = igv;
            // numerically stable logsigmoid
            g_lf[o] = fminf(fgv, 0.f) - log1pf(expf(-fabsf(fgv)));
        }
    }
}

// ---------------- sequential scan per (b,n): cumsum + running max ----------------
__global__ void scan_kernel() {
    int bn = blockIdx.x * blockDim.x + threadIdx.x;
    if (bn >= Bn * NHn) return;
    int base = bn * Sn;
    float c = 0.f, Mx = -INFINITY;
    for (int s = 0; s < Sn; s++) {
        c += g_lf[base + s];
        float a = g_ig[base + s] - c;
        Mx = fmaxf(Mx, a);
        g_a[base + s] = a;
        g_M[base + s] = Mx;
        g_nfl[base + s] = expf(-(c + Mx));  // exp(-m_s), m_s = c_s + Mx_s
    }
}

// ---------------- mLSTM cell: one block per (b, n, query row s) ----------------
__global__ void attn_kernel() {
    int rid = blockIdx.x;          // 0 .. B*NH*S-1
    int s  = rid % Sn;
    int bn = rid / Sn;
    int n  = bn % NHn;
    int b  = bn / NHn;
    int tid = threadIdx.x;         // 256

    __shared__ float4 sq[DHn / 4];     // 84
    __shared__ float  sw[Sn];          // weights
    __shared__ float  sred[33];

    const float4* qrow = (const float4*)&g_q[(b * Sn + s) * Hn + n * DHn];
    for (int i = tid; i < DHn / 4; i += 256) sq[i] = qrow[i];
    __syncthreads();

    int abase = bn * Sn;
    float Ms = g_M[abase + s];
    float scale = rsqrtf((float)DHn);

    // phase 1: w_t = (q.k_t)*scale * exp(a_t - M_s), accumulate sum
    float lsum = 0.f;
    for (int t = tid; t <= s; t += 256) {
        const float4* krow = (const float4*)&g_k[(b * Sn + t) * Hn + n * DHn];
        float d0 = 0.f, d1 = 0.f, d2 = 0.f, d3 = 0.f;
        #pragma unroll 4
        for (int i = 0; i < DHn / 4; i++) {
            float4 qv = sq[i];
            float4 kv = krow[i];
            d0 += qv.x * kv.x;
            d1 += qv.y * kv.y;
            d2 += qv.z * kv.z;
            d3 += qv.w * kv.w;
        }
        float w = (d0 + d1 + d2 + d3) * scale * expf(g_a[abase + t] - Ms);
        sw[t] = w;
        lsum += w;
    }
    #pragma unroll
    for (int o = 16; o > 0; o >>= 1) lsum += __shfl_down_sync(0xffffffffu, lsum, o);
    if ((tid & 31) == 0) sred[tid >> 5] = lsum;
    __syncthreads();
    if (tid == 0) {
        float tot = 0.f;
        #pragma unroll
        for (int w = 0; w < 8; w++) tot += sred[w];
        float nval = fmaxf(fabsf(tot), g_nfl[abase + s]);
        sred[32] = 1.f / (nval + 1e-6f);
    }
    __syncthreads();
    float inv = sred[32];

    // phase 2: h_d = inv * sum_t w_t * v[t,d]   (coalesced over d)
    for (int d = tid; d < DHn; d += 256) {
        const float* vcol = &g_v[b * Sn * Hn + n * DHn + d];
        float a0 = 0.f, a1 = 0.f, a2 = 0.f, a3 = 0.f;
        int t = 0;
        for (; t + 3 <= s; t += 4) {
            a0 += sw[t]     * vcol[(t)     * Hn];
            a1 += sw[t + 1] * vcol[(t + 1) * Hn];
            a2 += sw[t + 2] * vcol[(t + 2) * Hn];
            a3 += sw[t + 3] * vcol[(t + 3) * Hn];
        }
        for (; t <= s; t++) a0 += sw[t] * vcol[t * Hn];
        g_h[(b * Sn + s) * Hn + n * DHn + d] = (a0 + a1 + a2 + a3) * inv;
    }
}

// ---------------- per-head LN (scale only) + skip + SiLU(z) gate ----------------
__global__ void ln_gate_kernel(const float* __restrict__ ln_w,
                               const float* __restrict__ skip) {
    int rid = blockIdx.x;          // TOT*NH
    int p = rid >> 2;
    int n = rid & 3;
    int tid = threadIdx.x;         // 128
    const float* hrow = &g_h[p * Hn + n * DHn];

    float sum = 0.f, sq = 0.f;
    for (int d = tid; d < DHn; d += 128) {
        float v = hrow[d];
        sum += v; sq += v * v;
    }
    __shared__ float s1[4], s2[4], sbc[2];
    #pragma unroll
    for (int o = 16; o > 0; o >>= 1) {
        sum += __shfl_down_sync(0xffffffffu, sum, o);
        sq  += __shfl_down_sync(0xffffffffu, sq, o);
    }
    if ((tid & 31) == 0) { s1[tid >> 5] = sum; s2[tid >> 5] = sq; }
    __syncthreads();
    if (tid == 0) {
        float ts = s1[0] + s1[1] + s1[2] + s1[3];
        float tq = s2[0] + s2[1] + s2[2] + s2[3];
        float mu = ts / (float)DHn;
        float var = fmaxf(tq / (float)DHn - mu * mu, 0.f);
        sbc[0] = mu;
        sbc[1] = rsqrtf(var + 1e-5f);
    }
    __syncthreads();
    float mu = sbc[0], rs = sbc[1];
    for (int d = tid; d < DHn; d += 128) {
        int hidx = n * DHn + d;
        float hnv = (hrow[d] - mu) * rs * ln_w[hidx];
        float z = g_xinner[p * H2n + Hn + hidx];
        float sz = z / (1.f + expf(-z));
        g_hst[p * Hn + hidx] = (hnv + skip[hidx] * g_act[p * Hn + hidx]) * sz;
    }
}

// ---------------- launch ----------------
extern "C" void kernel_launch(void* const* d_in, const int* in_sizes, int n_in,
                              void* d_out, int out_size) {
    const float* x      = (const float*)d_in[0];
    const float* W_up   = (const float*)d_in[1];
    const float* conv_k = (const float*)d_in[2];
    const float* conv_b = (const float*)d_in[3];
    const float* Wq     = (const float*)d_in[4];
    const float* Wk     = (const float*)d_in[5];
    const float* Wv     = (const float*)d_in[6];
    const float* W_ig   = (const float*)d_in[7];
    const float* b_ig   = (const float*)d_in[8];
    const float* W_fg   = (const float*)d_in[9];
    const float* b_fg   = (const float*)d_in[10];
    const float* ln_w   = (const float*)d_in[11];
    const float* skip   = (const float*)d_in[12];
    const float* W_down = (const float*)d_in[13];
    float* out = (float*)d_out;

    void *p_xinner = nullptr, *p_hst = nullptr;
    cudaGetSymbolAddress(&p_xinner, g_xinner);
    cudaGetSymbolAddress(&p_hst, g_hst);

    // 1. up projection: (4096x1024) @ (1024x2688)
    sgemm_kernel<<<dim3(H2n / 64, TOT / 64), 256>>>(x, W_up, (float*)p_xinner,
                                                    TOT, H2n, En);
    // 2. causal depthwise conv + SiLU
    {
        int n = TOT * Hn;
        conv_silu_kernel<<<(n + 255) / 256, 256>>>(conv_k, conv_b);
    }
    // 3. headwise q,k,v projections
    {
        int n = TOT * Hn;
        headwise_kernel<<<(n + 255) / 256, 256>>>(Wq, Wk, Wv);
    }
    // 4. gate projections
    gates_kernel<<<TOT, 128>>>(W_ig, b_ig, W_fg, b_fg);
    // 5. per-(b,n) scan: cumsum(logsigmoid(fg)), running max
    scan_kernel<<<1, 8>>>();
    // 6. mLSTM cell
    attn_kernel<<<Bn * NHn * Sn, 256>>>();
    // 7. multi-head LN + skip + SiLU(z) gate
    ln_gate_kernel<<<TOT * NHn, 128>>>(ln_w, skip);
    // 8. down projection: (4096x1344) @ (1344x1024)
    sgemm_kernel<<<dim3(En / 64, TOT / 64), 256>>>((const float*)p_hst, W_down,
                                                   out, TOT, En, Hn);
}

// round 5
// speedup vs baseline: 3.0435x; 3.0435x over previous
#include <cuda_runtime.h>
#include <math.h>

// ---------------- problem constants ----------------
#define Bn   2
#define Sn   2048
#define En   1024
#define Hn   1344
#define H2n  2688
#define NHn  4
#define DHn  336
#define DH4  84           // DHn/4
#define TOT  (Bn*Sn)      // 4096 rows

// attention tiling
#define TQ   64
#define TK   64
#define DHP  344          // padded row stride (floats) for Q/V tiles
#define TKP  68           // padded row stride for K-transposed / W tiles
#define NQT  (Sn/TQ)      // 32

// dynamic smem layout (floats)
#define SM_Q    0
#define SM_KV   (TQ*DHP)                    // 22016
#define SM_W    (SM_KV + DHn*TKP)           // 22016+22848=44864  (KT is the larger use)
#define SM_M    (SM_W + TQ*TKP)             // +4352
#define SM_SUM  (SM_M + TQ)
#define SM_A    (SM_SUM + TQ)
#define SM_TOTF (SM_A + TK)
#define ATTN_SMEM_BYTES (SM_TOTF * 4)       // ~197.7 KB

// ---------------- device scratch (no allocs allowed) ----------------
__device__ float g_xinner[TOT * H2n];  // up-proj output: [x_m | z]
__device__ float g_act   [TOT * Hn];   // silu(conv(x_m))
__device__ float g_q     [TOT * Hn];
__device__ float g_k     [TOT * Hn];
__device__ float g_v     [TOT * Hn];
__device__ float g_h     [TOT * Hn];   // mLSTM cell output
__device__ float g_hst   [TOT * Hn];   // post-LN/skip/gate
__device__ float g_ig    [Bn*NHn*Sn];
__device__ float g_lf    [Bn*NHn*Sn];  // logsigmoid(fg)
__device__ float g_a     [Bn*NHn*Sn];  // a_t = ig_t - c_t
__device__ float g_M     [Bn*NHn*Sn];  // running max of a
__device__ float g_nfl   [Bn*NHn*Sn];  // exp(-m_s)

// ---------------- fp32 tiled GEMM: C = A(MxK) * B(KxN) ----------------
// BM=128, BN=64, BK=16, 256 threads, 8x4 micro-tile.
// Requires M%128==0, N%64==0, K%16==0 (all shapes satisfy this).
__global__ void sgemm128_kernel(const float* __restrict__ A,
                                const float* __restrict__ B,
                                float* __restrict__ C,
                                int M, int N, int Kd) {
    const int BM = 128, BN = 64, BK = 16;
    __shared__ float As[BK][BM];
    __shared__ float Bs[BK][BN];
    int bx = blockIdx.x;              // N tile
    int by = blockIdx.y;              // M tile
    int tid = threadIdx.x;            // 0..255
    int tx = tid & 15;                // 0..15 (N dir, 4 each)
    int ty = tid >> 4;                // 0..15 (M dir, 8 each)

    // A-load mapping: each thread loads 8 contiguous elems of one A row-chunk
    int ar = tid >> 1;                // row within tile (0..127)
    int ac = (tid & 1) * 8;           // col 0 or 8
    // B-load mapping: each thread loads 4 contiguous
    int br = tid >> 4;                // 0..15
    int bc = (tid & 15) * 4;

    float acc[8][4];
    #pragma unroll
    for (int i = 0; i < 8; i++)
        #pragma unroll
        for (int j = 0; j < 4; j++) acc[i][j] = 0.f;

    const float* Arow = A + (size_t)(by * BM + ar) * Kd + ac;
    const float* Brow = B + (size_t)br * N + bx * BN + bc;

    for (int k0 = 0; k0 < Kd; k0 += BK) {
        float4 a0 = *(const float4*)(Arow + k0);
        float4 a1 = *(const float4*)(Arow + k0 + 4);
        float4 b0 = *(const float4*)(Brow + (size_t)k0 * N);
        As[ac + 0][ar] = a0.x; As[ac + 1][ar] = a0.y;
        As[ac + 2][ar] = a0.z; As[ac + 3][ar] = a0.w;
        As[ac + 4][ar] = a1.x; As[ac + 5][ar] = a1.y;
        As[ac + 6][ar] = a1.z; As[ac + 7][ar] = a1.w;
        *(float4*)&Bs[br][bc] = b0;
        __syncthreads();
        #pragma unroll
        for (int kk = 0; kk < BK; kk++) {
            float4 av0 = *(const float4*)&As[kk][ty * 8];
            float4 av1 = *(const float4*)&As[kk][ty * 8 + 4];
            float4 bv  = *(const float4*)&Bs[kk][tx * 4];
            float a[8] = {av0.x, av0.y, av0.z, av0.w, av1.x, av1.y, av1.z, av1.w};
            float b[4] = {bv.x, bv.y, bv.z, bv.w};
            #pragma unroll
            for (int i = 0; i < 8; i++)
                #pragma unroll
                for (int j = 0; j < 4; j++) acc[i][j] += a[i] * b[j];
        }
        __syncthreads();
    }
    #pragma unroll
    for (int i = 0; i < 8; i++) {
        float4 o = make_float4(acc[i][0], acc[i][1], acc[i][2], acc[i][3]);
        *(float4*)&C[(size_t)(by * BM + ty * 8 + i) * N + bx * BN + tx * 4] = o;
    }
}

// ---------------- causal depthwise conv (K=4) + bias + SiLU ----------------
__global__ void conv_silu_kernel(const float* __restrict__ conv_k,
                                 const float* __restrict__ conv_b) {
    int idx = blockIdx.x * blockDim.x + threadIdx.x;
    if (idx >= TOT * Hn) return;
    int h = idx % Hn;
    int p = idx / Hn;          // b*S + s
    int s = p % Sn;
    float acc = conv_b[h];
    #pragma unroll
    for (int j = 0; j < 4; j++) {
        int t = s - 3 + j;
        if (t >= 0) acc += g_xinner[(size_t)(p - s + t) * H2n + h] * conv_k[j * Hn + h];
    }
    float sg = 1.f / (1.f + expf(-acc));
    g_act[idx] = acc * sg;
}

// ---------------- headwise 4x4 block-diagonal projections ----------------
__global__ void headwise_kernel(const float* __restrict__ Wq,
                                const float* __restrict__ Wk,
                                const float* __restrict__ Wv) {
    int idx = blockIdx.x * blockDim.x + threadIdx.x;
    if (idx >= TOT * Hn) return;
    int h = idx % Hn;
    int p = idx / Hn;
    int head = h >> 2;
    int o = h & 3;
    const float* a  = &g_act[(size_t)p * Hn + head * 4];
    const float* xm = &g_xinner[(size_t)p * H2n + head * 4];
    float q = 0.f, k = 0.f, v = 0.f;
    #pragma unroll
    for (int d = 0; d < 4; d++) {
        q += a[d]  * Wq[head * 16 + d * 4 + o];
        k += a[d]  * Wk[head * 16 + d * 4 + o];
        v += xm[d] * Wv[head * 16 + d * 4 + o];
    }
    g_q[idx] = q; g_k[idx] = k; g_v[idx] = v;
}

// ---------------- input/forget gate projections ----------------
__global__ void gates_kernel(const float* __restrict__ W_ig,
                             const float* __restrict__ b_ig,
                             const float* __restrict__ W_fg,
                             const float* __restrict__ b_fg) {
    int p = blockIdx.x;          // 0..TOT-1
    int tid = threadIdx.x;       // 128
    float aig[4] = {0, 0, 0, 0}, afg[4] = {0, 0, 0, 0};
    const float4* wig4 = (const float4*)W_ig;
    const float4* wfg4 = (const float4*)W_fg;
    for (int i = tid; i < 3 * Hn; i += 128) {
        float g;
        if (i < Hn)            g = g_q[(size_t)p * Hn + i];
        else if (i < 2 * Hn)   g = g_k[(size_t)p * Hn + i - Hn];
        else                   g = g_v[(size_t)p * Hn + i - 2 * Hn];
        float4 wi = wig4[i];
        float4 wf = wfg4[i];
        aig[0] += g * wi.x; aig[1] += g * wi.y; aig[2] += g * wi.z; aig[3] += g * wi.w;
        afg[0] += g * wf.x; afg[1] += g * wf.y; afg[2] += g * wf.z; afg[3] += g * wf.w;
    }
    __shared__ float sred[4];
    float rig[4], rfg[4];
    #pragma unroll
    for (int n = 0; n < 4; n++) {
        float v = aig[n];
        #pragma unroll
        for (int o = 16; o > 0; o >>= 1) v += __shfl_down_sync(0xffffffffu, v, o);
        if ((tid & 31) == 0) sred[tid >> 5] = v;
        __syncthreads();
        if (tid == 0) rig[n] = sred[0] + sred[1] + sred[2] + sred[3];
        __syncthreads();
        v = afg[n];
        #pragma unroll
        for (int o = 16; o > 0; o >>= 1) v += __shfl_down_sync(0xffffffffu, v, o);
        if ((tid & 31) == 0) sred[tid >> 5] = v;
        __syncthreads();
        if (tid == 0) rfg[n] = sred[0] + sred[1] + sred[2] + sred[3];
        __syncthreads();
    }
    if (tid == 0) {
        int b = p / Sn, s = p % Sn;
        #pragma unroll
        for (int n = 0; n < 4; n++) {
            float igv = rig[n] + b_ig[n];
            float fgv = rfg[n] + b_fg[n];
            int o = (b * NHn + n) * Sn + s;
            g_ig[o] = igv;
            g_lf[o] = fminf(fgv, 0.f) - log1pf(expf(-fabsf(fgv)));
        }
    }
}

// ---------------- sequential scan per (b,n) ----------------
__global__ void scan_kernel() {
    int bn = blockIdx.x * blockDim.x + threadIdx.x;
    if (bn >= Bn * NHn) return;
    int base = bn * Sn;
    float c = 0.f, Mx = -INFINITY;
    for (int s = 0; s < Sn; s++) {
        c += g_lf[base + s];
        float a = g_ig[base + s] - c;
        Mx = fmaxf(Mx, a);
        g_a[base + s] = a;
        g_M[base + s] = Mx;
        g_nfl[base + s] = expf(-(c + Mx));
    }
}

// ---------------- tiled mLSTM cell ----------------
// grid: (NQT, B*NH), 256 threads, ~197 KB dynamic smem.
// Stabilizer m_s is precomputed -> no online rescaling: masked GEMM, exp, GEMM.
__global__ void attn_tiled_kernel() {
    extern __shared__ float smem[];
    float* sQ   = smem + SM_Q;     // [TQ][DHP]
    float* sKV  = smem + SM_KV;    // KT: [DHn][TKP]  /  V: [TK][DHP]
    float* sW   = smem + SM_W;     // [TQ][TKP]
    float* sM   = smem + SM_M;     // [TQ]
    float* sSum = smem + SM_SUM;   // [TQ]
    float* sA   = smem + SM_A;     // [TK]

    int bn = blockIdx.y;
    int n = bn % NHn, b = bn / NHn;
    int qt = (NQT - 1) - blockIdx.x;   // longest blocks first
    int q0 = qt * TQ;
    int tid = threadIdx.x;
    int tx = tid & 15, ty = tid >> 4;
    int abase = bn * Sn;

    // load Q tile
    for (int i = tid; i < TQ * DH4; i += 256) {
        int r = i / DH4, c = i % DH4;
        ((float4*)(sQ + r * DHP))[c] =
            ((const float4*)&g_q[(size_t)(b * Sn + q0 + r) * Hn + n * DHn])[c];
    }
    if (tid < TQ) {
        sM[tid] = g_M[abase + q0 + tid];
        sSum[tid] = 0.f;
    }
    __syncthreads();

    float acc[4][21];
    #pragma unroll
    for (int i = 0; i < 4; i++)
        #pragma unroll
        for (int j = 0; j < 21; j++) acc[i][j] = 0.f;

    const float scale = rsqrtf((float)DHn);
    int nkt = qt + 1;

    for (int kt = 0; kt < nkt; kt++) {
        int k0 = kt * TK;
        __syncthreads();   // previous V reads done before overwriting sKV
        // load K tile TRANSPOSED: sKV[dim][key]
        for (int i = tid; i < TK * DH4; i += 256) {
            int r = i / DH4, c4 = i % DH4;
            float4 kq = ((const float4*)&g_k[(size_t)(b * Sn + k0 + r) * Hn + n * DHn])[c4];
            sKV[(c4 * 4 + 0) * TKP + r] = kq.x;
            sKV[(c4 * 4 + 1) * TKP + r] = kq.y;
            sKV[(c4 * 4 + 2) * TKP + r] = kq.z;
            sKV[(c4 * 4 + 3) * TKP + r] = kq.w;
        }
        if (tid < TK) sA[tid] = g_a[abase + k0 + tid];
        __syncthreads();

        // QK^T microtile: 4 queries x 4 keys per thread
        float w[4][4];
        #pragma unroll
        for (int i = 0; i < 4; i++)
            #pragma unroll
            for (int j = 0; j < 4; j++) w[i][j] = 0.f;

        #pragma unroll 2
        for (int c = 0; c < DH4; c++) {
            float4 qv[4], kv[4];
            #pragma unroll
            for (int i = 0; i < 4; i++)
                qv[i] = *(const float4*)(sQ + (ty * 4 + i) * DHP + c * 4);
            #pragma unroll
            for (int u = 0; u < 4; u++)
                kv[u] = *(const float4*)(sKV + (c * 4 + u) * TKP + tx * 4);
            #pragma unroll
            for (int i = 0; i < 4; i++) {
                w[i][0] += qv[i].x * kv[0].x + qv[i].y * kv[1].x + qv[i].z * kv[2].x + qv[i].w * kv[3].x;
                w[i][1] += qv[i].x * kv[0].y + qv[i].y * kv[1].y + qv[i].z * kv[2].y + qv[i].w * kv[3].y;
                w[i][2] += qv[i].x * kv[0].z + qv[i].y * kv[1].z + qv[i].z * kv[2].z + qv[i].w * kv[3].z;
                w[i][3] += qv[i].x * kv[0].w + qv[i].y * kv[1].w + qv[i].z * kv[2].w + qv[i].w * kv[3].w;
            }
        }

        // scale * exp(a_t - m_s), causal mask, row sums
        float rsum[4];
        #pragma unroll
        for (int i = 0; i < 4; i++) {
            int q = q0 + ty * 4 + i;
            float Ms = sM[ty * 4 + i];
            float4 wo;
            float* wp = &wo.x;
            rsum[i] = 0.f;
            #pragma unroll
            for (int j = 0; j < 4; j++) {
                int t = k0 + tx * 4 + j;
                float val = (t <= q) ? w[i][j] * scale * __expf(sA[tx * 4 + j] - Ms) : 0.f;
                wp[j] = val;
                rsum[i] += val;
            }
            *(float4*)&sW[(ty * 4 + i) * TKP + tx * 4] = wo;
        }
        #pragma unroll
        for (int o = 8; o > 0; o >>= 1)
            #pragma unroll
            for (int i = 0; i < 4; i++)
                rsum[i] += __shfl_down_sync(0xffffffffu, rsum[i], o, 16);
        if (tx == 0) {
            #pragma unroll
            for (int i = 0; i < 4; i++) sSum[ty * 4 + i] += rsum[i];
        }
        __syncthreads();   // sW ready; QK done with sKV

        // load V tile (row-major): sKV[key][dim]
        for (int i = tid; i < TK * DH4; i += 256) {
            int r = i / DH4, c4 = i % DH4;
            ((float4*)(sKV + r * DHP))[c4] =
                ((const float4*)&g_v[(size_t)(b * Sn + k0 + r) * Hn + n * DHn])[c4];
        }
        __syncthreads();

        // PV: acc[q][d] += w[q][t] * v[t][d]
        #pragma unroll 1
        for (int t4 = 0; t4 < TK / 4; t4++) {
            float4 wv[4];
            #pragma unroll
            for (int i = 0; i < 4; i++)
                wv[i] = ((const float4*)&sW[(ty * 4 + i) * TKP])[t4];
            #pragma unroll
            for (int u = 0; u < 4; u++) {
                int t = t4 * 4 + u;
                const float* vrow = sKV + t * DHP + tx;
                float wu[4] = {(&wv[0].x)[u], (&wv[1].x)[u], (&wv[2].x)[u], (&wv[3].x)[u]};
                #pragma unroll
                for (int j = 0; j < 21; j++) {
                    float vv = vrow[16 * j];
                    acc[0][j] += wu[0] * vv;
                    acc[1][j] += wu[1] * vv;
                    acc[2][j] += wu[2] * vv;
                    acc[3][j] += wu[3] * vv;
                }
            }
        }
    }
    __syncthreads();

    // epilogue: normalize and store
    #pragma unroll
    for (int i = 0; i < 4; i++) {
        int q = ty * 4 + i;
        float s = sSum[q];
        float nfl = g_nfl[abase + q0 + q];
        float inv = 1.f / (fmaxf(fabsf(s), nfl) + 1e-6f);
        float* orow = &g_h[(size_t)(b * Sn + q0 + q) * Hn + n * DHn];
        #pragma unroll
        for (int j = 0; j < 21; j++)
            orow[tx + 16 * j] = acc[i][j] * inv;
    }
}

// ---------------- per-head LN + skip + SiLU(z) gate ----------------
__global__ void ln_gate_kernel(const float* __restrict__ ln_w,
                               const float* __restrict__ skip) {
    int rid = blockIdx.x;          // TOT*NH
    int p = rid >> 2;
    int n = rid & 3;
    int tid = threadIdx.x;         // 128
    const float* hrow = &g_h[(size_t)p * Hn + n * DHn];

    float sum = 0.f, sq = 0.f;
    for (int d = tid; d < DHn; d += 128) {
        float v = hrow[d];
        sum += v; sq += v * v;
    }
    __shared__ float s1[4], s2[4], sbc[2];
    #pragma unroll
    for (int o = 16; o > 0; o >>= 1) {
        sum += __shfl_down_sync(0xffffffffu, sum, o);
        sq  += __shfl_down_sync(0xffffffffu, sq, o);
    }
    if ((tid & 31) == 0) { s1[tid >> 5] = sum; s2[tid >> 5] = sq; }
    __syncthreads();
    if (tid == 0) {
        float ts = s1[0] + s1[1] + s1[2] + s1[3];
        float tq = s2[0] + s2[1] + s2[2] + s2[3];
        float mu = ts / (float)DHn;
        float var = fmaxf(tq / (float)DHn - mu * mu, 0.f);
        sbc[0] = mu;
        sbc[1] = rsqrtf(var + 1e-5f);
    }
    __syncthreads();
    float mu = sbc[0], rs = sbc[1];
    for (int d = tid; d < DHn; d += 128) {
        int hidx = n * DHn + d;
        float hnv = (hrow[d] - mu) * rs * ln_w[hidx];
        float z = g_xinner[(size_t)p * H2n + Hn + hidx];
        float sz = z / (1.f + expf(-z));
        g_hst[(size_t)p * Hn + hidx] = (hnv + skip[hidx] * g_act[(size_t)p * Hn + hidx]) * sz;
    }
}

// ---------------- launch ----------------
extern "C" void kernel_launch(void* const* d_in, const int* in_sizes, int n_in,
                              void* d_out, int out_size) {
    const float* x      = (const float*)d_in[0];
    const float* conv_k = (const float*)d_in[2];
    const float* conv_b = (const float*)d_in[3];
    const float* Wq     = (const float*)d_in[4];
    const float* Wk     = (const float*)d_in[5];
    const float* Wv     = (const float*)d_in[6];
    const float* W_ig   = (const float*)d_in[7];
    const float* b_ig   = (const float*)d_in[8];
    const float* W_fg   = (const float*)d_in[9];
    const float* b_fg   = (const float*)d_in[10];
    const float* ln_w   = (const float*)d_in[11];
    const float* skip   = (const float*)d_in[12];
    const float* W_down = (const float*)d_in[13];
    const float* W_up   = (const float*)d_in[1];
    float* out = (float*)d_out;

    void *p_xinner = nullptr, *p_hst = nullptr;
    cudaGetSymbolAddress(&p_xinner, g_xinner);
    cudaGetSymbolAddress(&p_hst, g_hst);

    static bool attr_set = false;
    if (!attr_set) {
        cudaFuncSetAttribute(attn_tiled_kernel,
                             cudaFuncAttributeMaxDynamicSharedMemorySize,
                             ATTN_SMEM_BYTES);
        attr_set = true;
    }

    // 1. up projection: (4096x1024) @ (1024x2688)
    sgemm128_kernel<<<dim3(H2n / 64, TOT / 128), 256>>>(x, W_up, (float*)p_xinner,
                                                        TOT, H2n, En);
    // 2. causal depthwise conv + SiLU
    {
        int n = TOT * Hn;
        conv_silu_kernel<<<(n + 255) / 256, 256>>>(conv_k, conv_b);
    }
    // 3. headwise q,k,v projections
    {
        int n = TOT * Hn;
        headwise_kernel<<<(n + 255) / 256, 256>>>(Wq, Wk, Wv);
    }
    // 4. gate projections
    gates_kernel<<<TOT, 128>>>(W_ig, b_ig, W_fg, b_fg);
    // 5. per-(b,n) scan
    scan_kernel<<<1, 8>>>();
    // 6. tiled mLSTM cell
    attn_tiled_kernel<<<dim3(NQT, Bn * NHn), 256, ATTN_SMEM_BYTES>>>();
    // 7. multi-head LN + skip + SiLU(z) gate
    ln_gate_kernel<<<TOT * NHn, 128>>>(ln_w, skip);
    // 8. down projection: (4096x1344) @ (1344x1024)
    sgemm128_kernel<<<dim3(En / 64, TOT / 128), 256>>>((const float*)p_hst, W_down,
                                                       out, TOT, En, Hn);
}

// round 6
// speedup vs baseline: 4.0427x; 1.3283x over previous
#include <cuda_runtime.h>
#include <math.h>
#include <stdint.h>

// ---------------- problem constants ----------------
#define Bn   2
#define Sn   2048
#define En   1024
#define Hn   1344
#define H2n  2688
#define NHn  4
#define DHn  336
#define DH4  84           // DHn/4
#define TOT  (Bn*Sn)      // 4096 rows

// attention tiling
#define TQ   64
#define TK   64
#define DHP  344          // padded row stride (floats) for Q/V tiles
#define TKP  68           // padded row stride for K-transposed / W tiles
#define NQT  (Sn/TQ)      // 32

// dynamic smem layout (floats)
#define SM_Q    0
#define SM_KV   (TQ*DHP)
#define SM_W    (SM_KV + DHn*TKP)
#define SM_M    (SM_W + TQ*TKP)
#define SM_SUM  (SM_M + TQ)
#define SM_A    (SM_SUM + TQ)
#define SM_TOTF (SM_A + TK)
#define ATTN_SMEM_BYTES (SM_TOTF * 4)       // ~197.7 KB

// ---------------- device scratch (no allocs allowed) ----------------
__device__ float g_xinner[TOT * H2n];  // up-proj output: [x_m | z]
__device__ float g_act   [TOT * Hn];   // silu(conv(x_m))
__device__ float g_q     [TOT * Hn];
__device__ float g_k     [TOT * Hn];
__device__ float g_v     [TOT * Hn];
__device__ float g_h     [TOT * Hn];   // mLSTM cell output
__device__ float g_hst   [TOT * Hn];   // post-LN/skip/gate
__device__ float g_ig    [Bn*NHn*Sn];
__device__ float g_lf    [Bn*NHn*Sn];  // logsigmoid(fg)
__device__ float g_a     [Bn*NHn*Sn];  // a_t = ig_t - c_t
__device__ float g_M     [Bn*NHn*Sn];  // running max of a
__device__ float g_nfl   [Bn*NHn*Sn];  // exp(-m_s)

// ---------------- tf32 helpers ----------------
__device__ __forceinline__ uint32_t f2tf32(float x) {
    uint32_t r;
    asm("cvt.rna.tf32.f32 %0, %1;" : "=r"(r) : "f"(x));
    return r;
}

__device__ __forceinline__ void mma_tf32(float* c, const uint32_t* a, const uint32_t* b) {
    asm volatile(
        "mma.sync.aligned.m16n8k8.row.col.f32.tf32.tf32.f32 "
        "{%0,%1,%2,%3}, {%4,%5,%6,%7}, {%8,%9}, {%0,%1,%2,%3};\n"
        : "+f"(c[0]), "+f"(c[1]), "+f"(c[2]), "+f"(c[3])
        : "r"(a[0]), "r"(a[1]), "r"(a[2]), "r"(a[3]), "r"(b[0]), "r"(b[1]));
}

// ---------------- tensor-core tf32 GEMM: C = A(MxK) @ B(KxN), row-major ----------------
// CTA tile 128x128, BK=16, 256 threads = 8 warps (2 along M x 4 along N),
// warp tile 64x32 (4 m16-tiles x 4 n8-tiles). Double-buffered smem.
// A staged as As[m][k] stride 20 (conflict-free frag loads: bank 20*mq+k distinct).
// B staged as Bs[k][n] stride 136 (bank 8*k+nq distinct).
// Requires M%128==0, N%128==0, K%16==0.
#define ASTRIDE 20
#define BSTRIDE 136
__global__ __launch_bounds__(256) void mma_gemm_kernel(
    const float* __restrict__ A, const float* __restrict__ B,
    float* __restrict__ C, int M, int N, int K)
{
    __shared__ uint32_t As[2][128 * ASTRIDE];
    __shared__ uint32_t Bs[2][16 * BSTRIDE];

    int tid  = threadIdx.x;
    int lane = tid & 31, warp = tid >> 5;
    int wm = warp & 1, wn = warp >> 1;
    int bx = blockIdx.x, by = blockIdx.y;

    int ar  = tid & 127;        // A stage row (m)
    int ach = tid >> 7;         // A stage col half (k: 0..7 or 8..15)
    int br  = tid >> 4;         // B stage row (k)
    int bc  = (tid & 15) * 8;   // B stage col base (n)

    const float* Ap = A + (size_t)(by * 128 + ar) * K + ach * 8;
    const float* Bp = B + (size_t)br * N + bx * 128 + bc;

    float acc[4][4][4];
    #pragma unroll
    for (int mt = 0; mt < 4; mt++)
        #pragma unroll
        for (int nt = 0; nt < 4; nt++)
            #pragma unroll
            for (int e = 0; e < 4; e++) acc[mt][nt][e] = 0.f;

    int nk = K >> 4;
    float4 ra0, ra1, rb0, rb1;

    // prologue: load k-tile 0
    ra0 = *(const float4*)(Ap);
    ra1 = *(const float4*)(Ap + 4);
    rb0 = *(const float4*)(Bp);
    rb1 = *(const float4*)(Bp + 4);
    {
        int ab = ar * ASTRIDE + ach * 8;
        As[0][ab + 0] = f2tf32(ra0.x); As[0][ab + 1] = f2tf32(ra0.y);
        As[0][ab + 2] = f2tf32(ra0.z); As[0][ab + 3] = f2tf32(ra0.w);
        As[0][ab + 4] = f2tf32(ra1.x); As[0][ab + 5] = f2tf32(ra1.y);
        As[0][ab + 6] = f2tf32(ra1.z); As[0][ab + 7] = f2tf32(ra1.w);
        int bb = br * BSTRIDE + bc;
        Bs[0][bb + 0] = f2tf32(rb0.x); Bs[0][bb + 1] = f2tf32(rb0.y);
        Bs[0][bb + 2] = f2tf32(rb0.z); Bs[0][bb + 3] = f2tf32(rb0.w);
        Bs[0][bb + 4] = f2tf32(rb1.x); Bs[0][bb + 5] = f2tf32(rb1.y);
        Bs[0][bb + 6] = f2tf32(rb1.z); Bs[0][bb + 7] = f2tf32(rb1.w);
    }
    __syncthreads();

    int p = 0;
    for (int k0 = 0; k0 < nk; k0++) {
        if (k0 + 1 < nk) {
            const float* An = Ap + (size_t)(k0 + 1) * 16;
            const float* Bnp = Bp + (size_t)(k0 + 1) * 16 * N;
            ra0 = *(const float4*)(An);
            ra1 = *(const float4*)(An + 4);
            rb0 = *(const float4*)(Bnp);
            rb1 = *(const float4*)(Bnp + 4);
        }
        // compute two k8 halves from buffer p
        #pragma unroll
        for (int h = 0; h < 2; h++) {
            int kb = h * 8 + (lane & 3);
            uint32_t af[4][4], bf[4][2];
            #pragma unroll
            for (int mt = 0; mt < 4; mt++) {
                int m = wm * 64 + mt * 16 + (lane >> 2);
                af[mt][0] = As[p][m * ASTRIDE + kb];
                af[mt][1] = As[p][(m + 8) * ASTRIDE + kb];
                af[mt][2] = As[p][m * ASTRIDE + kb + 4];
                af[mt][3] = As[p][(m + 8) * ASTRIDE + kb + 4];
            }
            #pragma unroll
            for (int nt = 0; nt < 4; nt++) {
                int n = wn * 32 + nt * 8 + (lane >> 2);
                bf[nt][0] = Bs[p][kb * BSTRIDE + n];
                bf[nt][1] = Bs[p][(kb + 4) * BSTRIDE + n];
            }
            #pragma unroll
            for (int mt = 0; mt < 4; mt++)
                #pragma unroll
                for (int nt = 0; nt < 4; nt++)
                    mma_tf32(acc[mt][nt], af[mt], bf[nt]);
        }
        if (k0 + 1 < nk) {
            int q = p ^ 1;
            int ab = ar * ASTRIDE + ach * 8;
            As[q][ab + 0] = f2tf32(ra0.x); As[q][ab + 1] = f2tf32(ra0.y);
            As[q][ab + 2] = f2tf32(ra0.z); As[q][ab + 3] = f2tf32(ra0.w);
            As[q][ab + 4] = f2tf32(ra1.x); As[q][ab + 5] = f2tf32(ra1.y);
            As[q][ab + 6] = f2tf32(ra1.z); As[q][ab + 7] = f2tf32(ra1.w);
            int bb = br * BSTRIDE + bc;
            Bs[q][bb + 0] = f2tf32(rb0.x); Bs[q][bb + 1] = f2tf32(rb0.y);
            Bs[q][bb + 2] = f2tf32(rb0.z); Bs[q][bb + 3] = f2tf32(rb0.w);
            Bs[q][bb + 4] = f2tf32(rb1.x); Bs[q][bb + 5] = f2tf32(rb1.y);
            Bs[q][bb + 6] = f2tf32(rb1.z); Bs[q][bb + 7] = f2tf32(rb1.w);
            __syncthreads();
            p = q;
        }
    }

    // epilogue
    #pragma unroll
    for (int mt = 0; mt < 4; mt++) {
        int row = by * 128 + wm * 64 + mt * 16 + (lane >> 2);
        #pragma unroll
        for (int nt = 0; nt < 4; nt++) {
            int col = bx * 128 + wn * 32 + nt * 8 + 2 * (lane & 3);
            float2 v0 = make_float2(acc[mt][nt][0], acc[mt][nt][1]);
            float2 v1 = make_float2(acc[mt][nt][2], acc[mt][nt][3]);
            *(float2*)&C[(size_t)row * N + col] = v0;
            *(float2*)&C[(size_t)(row + 8) * N + col] = v1;
        }
    }
}

// ---------------- causal depthwise conv (K=4) + bias + SiLU ----------------
__global__ void conv_silu_kernel(const float* __restrict__ conv_k,
                                 const float* __restrict__ conv_b) {
    int idx = blockIdx.x * blockDim.x + threadIdx.x;
    if (idx >= TOT * Hn) return;
    int h = idx % Hn;
    int p = idx / Hn;          // b*S + s
    int s = p % Sn;
    float acc = conv_b[h];
    #pragma unroll
    for (int j = 0; j < 4; j++) {
        int t = s - 3 + j;
        if (t >= 0) acc += g_xinner[(size_t)(p - s + t) * H2n + h] * conv_k[j * Hn + h];
    }
    float sg = 1.f / (1.f + expf(-acc));
    g_act[idx] = acc * sg;
}

// ---------------- headwise 4x4 block-diagonal projections ----------------
__global__ void headwise_kernel(const float* __restrict__ Wq,
                                const float* __restrict__ Wk,
                                const float* __restrict__ Wv) {
    int idx = blockIdx.x * blockDim.x + threadIdx.x;
    if (idx >= TOT * Hn) return;
    int h = idx % Hn;
    int p = idx / Hn;
    int head = h >> 2;
    int o = h & 3;
    const float* a  = &g_act[(size_t)p * Hn + head * 4];
    const float* xm = &g_xinner[(size_t)p * H2n + head * 4];
    float q = 0.f, k = 0.f, v = 0.f;
    #pragma unroll
    for (int d = 0; d < 4; d++) {
        q += a[d]  * Wq[head * 16 + d * 4 + o];
        k += a[d]  * Wk[head * 16 + d * 4 + o];
        v += xm[d] * Wv[head * 16 + d * 4 + o];
    }
    g_q[idx] = q; g_k[idx] = k; g_v[idx] = v;
}

// ---------------- input/forget gate projections ----------------
// GR rows per block: amortizes the 128KB weight read across rows.
#define GR 4
__global__ void gates_kernel(const float* __restrict__ W_ig,
                             const float* __restrict__ b_ig,
                             const float* __restrict__ W_fg,
                             const float* __restrict__ b_fg) {
    int p0 = blockIdx.x * GR;
    int tid = threadIdx.x;       // 256
    int lane = tid & 31, warp = tid >> 5;
    float acc[GR][8];
    #pragma unroll
    for (int r = 0; r < GR; r++)
        #pragma unroll
        for (int v = 0; v < 8; v++) acc[r][v] = 0.f;

    const float4* wig4 = (const float4*)W_ig;
    const float4* wfg4 = (const float4*)W_fg;
    for (int i = tid; i < 3 * Hn; i += 256) {
        float4 wi = wig4[i];
        float4 wf = wfg4[i];
        const float* src;
        int off;
        if (i < Hn)          { src = g_q; off = i; }
        else if (i < 2 * Hn) { src = g_k; off = i - Hn; }
        else                 { src = g_v; off = i - 2 * Hn; }
        #pragma unroll
        for (int r = 0; r < GR; r++) {
            float g = src[(size_t)(p0 + r) * Hn + off];
            acc[r][0] += g * wi.x; acc[r][1] += g * wi.y;
            acc[r][2] += g * wi.z; acc[r][3] += g * wi.w;
            acc[r][4] += g * wf.x; acc[r][5] += g * wf.y;
            acc[r][6] += g * wf.z; acc[r][7] += g * wf.w;
        }
    }
    // intra-warp reduce all 32 values
    #pragma unroll
    for (int r = 0; r < GR; r++)
        #pragma unroll
        for (int v = 0; v < 8; v++)
            #pragma unroll
            for (int o = 16; o > 0; o >>= 1)
                acc[r][v] += __shfl_down_sync(0xffffffffu, acc[r][v], o);
    __shared__ float sred[8][32];
    if (lane == 0) {
        #pragma unroll
        for (int r = 0; r < GR; r++)
            #pragma unroll
            for (int v = 0; v < 8; v++)
                sred[warp][r * 8 + v] = acc[r][v];
    }
    __syncthreads();
    if (tid < 32) {
        float s = 0.f;
        #pragma unroll
        for (int w = 0; w < 8; w++) s += sred[w][tid];
        int r = tid >> 3, gsel = tid & 7;
        int pp = p0 + r;
        int b = pp / Sn, ss = pp % Sn;
        int n = gsel & 3;
        int o = (b * NHn + n) * Sn + ss;
        if (gsel < 4) {
            g_ig[o] = s + b_ig[n];
        } else {
            float fgv = s + b_fg[n];
            g_lf[o] = fminf(fgv, 0.f) - log1pf(expf(-fabsf(fgv)));
        }
    }
}

// ---------------- parallel scan per (b,n): cumsum(lf) + running max of a ----------------
// one block per bn, 256 threads x 8 contiguous elements each.
__global__ void scan_kernel() {
    __shared__ float sc[256];
    int bn = blockIdx.x;
    int tid = threadIdx.x;
    int off = bn * Sn + tid * 8;

    float locc[8];
    float run = 0.f;
    #pragma unroll
    for (int j = 0; j < 8; j++) { run += g_lf[off + j]; locc[j] = run; }

    // inclusive sum scan of per-thread totals
    sc[tid] = run;
    __syncthreads();
    for (int d = 1; d < 256; d <<= 1) {
        float add = (tid >= d) ? sc[tid - d] : 0.f;
        __syncthreads();
        sc[tid] += add;
        __syncthreads();
    }
    float coff = sc[tid] - run;   // exclusive prefix

    float av[8];
    float rmax = -INFINITY;
    #pragma unroll
    for (int j = 0; j < 8; j++) {
        locc[j] += coff;                       // c_s
        av[j] = g_ig[off + j] - locc[j];       // a_s
        rmax = fmaxf(rmax, av[j]);
    }
    __syncthreads();

    // inclusive max scan of per-thread maxima
    sc[tid] = rmax;
    __syncthreads();
    for (int d = 1; d < 256; d <<= 1) {
        float m = (tid >= d) ? sc[tid - d] : -INFINITY;
        __syncthreads();
        sc[tid] = fmaxf(sc[tid], m);
        __syncthreads();
    }
    float Mr = (tid == 0) ? -INFINITY : sc[tid - 1];

    #pragma unroll
    for (int j = 0; j < 8; j++) {
        Mr = fmaxf(Mr, av[j]);
        g_a[off + j] = av[j];
        g_M[off + j] = Mr;
        g_nfl[off + j] = expf(-(locc[j] + Mr));
    }
}

// ---------------- tiled mLSTM cell ----------------
// grid: (NQT, B*NH), 256 threads, ~197 KB dynamic smem.
__global__ void attn_tiled_kernel() {
    extern __shared__ float smem[];
    float* sQ   = smem + SM_Q;     // [TQ][DHP]
    float* sKV  = smem + SM_KV;    // KT: [DHn][TKP]  /  V: [TK][DHP]
    float* sW   = smem + SM_W;     // [TQ][TKP]
    float* sM   = smem + SM_M;     // [TQ]
    float* sSum = smem + SM_SUM;   // [TQ]
    float* sA   = smem + SM_A;     // [TK]

    int bn = blockIdx.y;
    int n = bn % NHn, b = bn / NHn;
    int qt = (NQT - 1) - blockIdx.x;   // longest blocks first
    int q0 = qt * TQ;
    int tid = threadIdx.x;
    int tx = tid & 15, ty = tid >> 4;
    int abase = bn * Sn;

    for (int i = tid; i < TQ * DH4; i += 256) {
        int r = i / DH4, c = i % DH4;
        ((float4*)(sQ + r * DHP))[c] =
            ((const float4*)&g_q[(size_t)(b * Sn + q0 + r) * Hn + n * DHn])[c];
    }
    if (tid < TQ) {
        sM[tid] = g_M[abase + q0 + tid];
        sSum[tid] = 0.f;
    }
    __syncthreads();

    float acc[4][21];
    #pragma unroll
    for (int i = 0; i < 4; i++)
        #pragma unroll
        for (int j = 0; j < 21; j++) acc[i][j] = 0.f;

    const float scale = rsqrtf((float)DHn);
    int nkt = qt + 1;

    for (int kt = 0; kt < nkt; kt++) {
        int k0 = kt * TK;
        __syncthreads();
        for (int i = tid; i < TK * DH4; i += 256) {
            int r = i / DH4, c4 = i % DH4;
            float4 kq = ((const float4*)&g_k[(size_t)(b * Sn + k0 + r) * Hn + n * DHn])[c4];
            sKV[(c4 * 4 + 0) * TKP + r] = kq.x;
            sKV[(c4 * 4 + 1) * TKP + r] = kq.y;
            sKV[(c4 * 4 + 2) * TKP + r] = kq.z;
            sKV[(c4 * 4 + 3) * TKP + r] = kq.w;
        }
        if (tid < TK) sA[tid] = g_a[abase + k0 + tid];
        __syncthreads();

        float w[4][4];
        #pragma unroll
        for (int i = 0; i < 4; i++)
            #pragma unroll
            for (int j = 0; j < 4; j++) w[i][j] = 0.f;

        #pragma unroll 2
        for (int c = 0; c < DH4; c++) {
            float4 qv[4], kv[4];
            #pragma unroll
            for (int i = 0; i < 4; i++)
                qv[i] = *(const float4*)(sQ + (ty * 4 + i) * DHP + c * 4);
            #pragma unroll
            for (int u = 0; u < 4; u++)
                kv[u] = *(const float4*)(sKV + (c * 4 + u) * TKP + tx * 4);
            #pragma unroll
            for (int i = 0; i < 4; i++) {
                w[i][0] += qv[i].x * kv[0].x + qv[i].y * kv[1].x + qv[i].z * kv[2].x + qv[i].w * kv[3].x;
                w[i][1] += qv[i].x * kv[0].y + qv[i].y * kv[1].y + qv[i].z * kv[2].y + qv[i].w * kv[3].y;
                w[i][2] += qv[i].x * kv[0].z + qv[i].y * kv[1].z + qv[i].z * kv[2].z + qv[i].w * kv[3].z;
                w[i][3] += qv[i].x * kv[0].w + qv[i].y * kv[1].w + qv[i].z * kv[2].w + qv[i].w * kv[3].w;
            }
        }

        float rsum[4];
        #pragma unroll
        for (int i = 0; i < 4; i++) {
            int q = q0 + ty * 4 + i;
            float Ms = sM[ty * 4 + i];
            float4 wo;
            float* wp = &wo.x;
            rsum[i] = 0.f;
            #pragma unroll
            for (int j = 0; j < 4; j++) {
                int t = k0 + tx * 4 + j;
                float val = (t <= q) ? w[i][j] * scale * __expf(sA[tx * 4 + j] - Ms) : 0.f;
                wp[j] = val;
                rsum[i] += val;
            }
            *(float4*)&sW[(ty * 4 + i) * TKP + tx * 4] = wo;
        }
        #pragma unroll
        for (int o = 8; o > 0; o >>= 1)
            #pragma unroll
            for (int i = 0; i < 4; i++)
                rsum[i] += __shfl_down_sync(0xffffffffu, rsum[i], o, 16);
        if (tx == 0) {
            #pragma unroll
            for (int i = 0; i < 4; i++) sSum[ty * 4 + i] += rsum[i];
        }
        __syncthreads();

        for (int i = tid; i < TK * DH4; i += 256) {
            int r = i / DH4, c4 = i % DH4;
            ((float4*)(sKV + r * DHP))[c4] =
                ((const float4*)&g_v[(size_t)(b * Sn + k0 + r) * Hn + n * DHn])[c4];
        }
        __syncthreads();

        #pragma unroll 1
        for (int t4 = 0; t4 < TK / 4; t4++) {
            float4 wv[4];
            #pragma unroll
            for (int i = 0; i < 4; i++)
                wv[i] = ((const float4*)&sW[(ty * 4 + i) * TKP])[t4];
            #pragma unroll
            for (int u = 0; u < 4; u++) {
                int t = t4 * 4 + u;
                const float* vrow = sKV + t * DHP + tx;
                float wu[4] = {(&wv[0].x)[u], (&wv[1].x)[u], (&wv[2].x)[u], (&wv[3].x)[u]};
                #pragma unroll
                for (int j = 0; j < 21; j++) {
                    float vv = vrow[16 * j];
                    acc[0][j] += wu[0] * vv;
                    acc[1][j] += wu[1] * vv;
                    acc[2][j] += wu[2] * vv;
                    acc[3][j] += wu[3] * vv;
                }
            }
        }
    }
    __syncthreads();

    #pragma unroll
    for (int i = 0; i < 4; i++) {
        int q = ty * 4 + i;
        float s = sSum[q];
        float nfl = g_nfl[abase + q0 + q];
        float inv = 1.f / (fmaxf(fabsf(s), nfl) + 1e-6f);
        float* orow = &g_h[(size_t)(b * Sn + q0 + q) * Hn + n * DHn];
        #pragma unroll
        for (int j = 0; j < 21; j++)
            orow[tx + 16 * j] = acc[i][j] * inv;
    }
}

// ---------------- per-head LN + skip + SiLU(z) gate ----------------
__global__ void ln_gate_kernel(const float* __restrict__ ln_w,
                               const float* __restrict__ skip) {
    int rid = blockIdx.x;          // TOT*NH
    int p = rid >> 2;
    int n = rid & 3;
    int tid = threadIdx.x;         // 128
    const float* hrow = &g_h[(size_t)p * Hn + n * DHn];

    float sum = 0.f, sq = 0.f;
    for (int d = tid; d < DHn; d += 128) {
        float v = hrow[d];
        sum += v; sq += v * v;
    }
    __shared__ float s1[4], s2[4], sbc[2];
    #pragma unroll
    for (int o = 16; o > 0; o >>= 1) {
        sum += __shfl_down_sync(0xffffffffu, sum, o);
        sq  += __shfl_down_sync(0xffffffffu, sq, o);
    }
    if ((tid & 31) == 0) { s1[tid >> 5] = sum; s2[tid >> 5] = sq; }
    __syncthreads();
    if (tid == 0) {
        float ts = s1[0] + s1[1] + s1[2] + s1[3];
        float tq = s2[0] + s2[1] + s2[2] + s2[3];
        float mu = ts / (float)DHn;
        float var = fmaxf(tq / (float)DHn - mu * mu, 0.f);
        sbc[0] = mu;
        sbc[1] = rsqrtf(var + 1e-5f);
    }
    __syncthreads();
    float mu = sbc[0], rs = sbc[1];
    for (int d = tid; d < DHn; d += 128) {
        int hidx = n * DHn + d;
        float hnv = (hrow[d] - mu) * rs * ln_w[hidx];
        float z = g_xinner[(size_t)p * H2n + Hn + hidx];
        float sz = z / (1.f + expf(-z));
        g_hst[(size_t)p * Hn + hidx] = (hnv + skip[hidx] * g_act[(size_t)p * Hn + hidx]) * sz;
    }
}

// ---------------- launch ----------------
extern "C" void kernel_launch(void* const* d_in, const int* in_sizes, int n_in,
                              void* d_out, int out_size) {
    const float* x      = (const float*)d_in[0];
    const float* W_up   = (const float*)d_in[1];
    const float* conv_k = (const float*)d_in[2];
    const float* conv_b = (const float*)d_in[3];
    const float* Wq     = (const float*)d_in[4];
    const float* Wk     = (const float*)d_in[5];
    const float* Wv     = (const float*)d_in[6];
    const float* W_ig   = (const float*)d_in[7];
    const float* b_ig   = (const float*)d_in[8];
    const float* W_fg   = (const float*)d_in[9];
    const float* b_fg   = (const float*)d_in[10];
    const float* ln_w   = (const float*)d_in[11];
    const float* skip   = (const float*)d_in[12];
    const float* W_down = (const float*)d_in[13];
    float* out = (float*)d_out;

    void *p_xinner = nullptr, *p_hst = nullptr;
    cudaGetSymbolAddress(&p_xinner, g_xinner);
    cudaGetSymbolAddress(&p_hst, g_hst);

    static bool attr_set = false;
    if (!attr_set) {
        cudaFuncSetAttribute(attn_tiled_kernel,
                             cudaFuncAttributeMaxDynamicSharedMemorySize,
                             ATTN_SMEM_BYTES);
        attr_set = true;
    }

    // 1. up projection: (4096x1024) @ (1024x2688) — tf32 tensor cores
    mma_gemm_kernel<<<dim3(H2n / 128, TOT / 128), 256>>>(x, W_up, (float*)p_xinner,
                                                         TOT, H2n, En);
    // 2. causal depthwise conv + SiLU
    {
        int n = TOT * Hn;
        conv_silu_kernel<<<(n + 255) / 256, 256>>>(conv_k, conv_b);
    }
    // 3. headwise q,k,v projections
    {
        int n = TOT * Hn;
        headwise_kernel<<<(n + 255) / 256, 256>>>(Wq, Wk, Wv);
    }
    // 4. gate projections (4 rows per block)
    gates_kernel<<<TOT / GR, 256>>>(W_ig, b_ig, W_fg, b_fg);
    // 5. per-(b,n) parallel scan
    scan_kernel<<<Bn * NHn, 256>>>();
    // 6. tiled mLSTM cell
    attn_tiled_kernel<<<dim3(NQT, Bn * NHn), 256, ATTN_SMEM_BYTES>>>();
    // 7. multi-head LN + skip + SiLU(z) gate
    ln_gate_kernel<<<TOT * NHn, 128>>>(ln_w, skip);
    // 8. down projection: (4096x1344) @ (1344x1024) — tf32 tensor cores
    mma_gemm_kernel<<<dim3(En / 128, TOT / 128), 256>>>((const float*)p_hst, W_down,
                                                        out, TOT, En, Hn);
}

// round 9
// speedup vs baseline: 4.5312x; 1.1208x over previous
#include <cuda_runtime.h>
#include <math.h>
#include <stdint.h>

// ---------------- problem constants ----------------
#define Bn   2
#define Sn   2048
#define En   1024
#define Hn   1344
#define H2n  2688
#define NHn  4
#define DHn  336
#define DH4  84           // DHn/4
#define DH2  168          // DHn/2 (dim pairs)
#define NPH  (Hn/4)       // 336 projection heads
#define TOT  (Bn*Sn)      // 4096 rows

// attention tiling
#define TQ   64
#define TK   64
#define DHP  344          // padded row stride (floats) for Q/V tiles
#define DHP2 (DHP/2)      // 172 u64 stride for V pairs
#define TKP  68           // padded row stride for W tile
#define TKP2 65           // u64 row stride for K dim-pair tile (odd -> conflict-free)
#define NQT  (Sn/TQ)      // 32

// dynamic smem layout (floats)
#define SM_Q    0
#define SM_KV   (TQ*DHP)                    // 22016: union{ K2 [168][65] u64 (21840 fl), V [64][344] fl (22016 fl) }
#define SM_W    (SM_KV + TQ*DHP)            // 44032
#define SM_M    (SM_W + TQ*TKP)             // 48384
#define SM_SUM  (SM_M + TQ)
#define SM_A    (SM_SUM + TQ)
#define SM_TOTF (SM_A + TK)
#define ATTN_SMEM_BYTES (SM_TOTF * 4)       // ~194.3 KB

typedef unsigned long long u64;

// ---------------- packed f32x2 helpers (FFMA2 path, full fp32 precision) ----------------
__device__ __forceinline__ void ffma2(u64& c, u64 a, u64 b) {
    asm("fma.rn.f32x2 %0, %1, %2, %0;" : "+l"(c) : "l"(a), "l"(b));
}
__device__ __forceinline__ u64 pack2(float lo, float hi) {
    u64 r; asm("mov.b64 %0, {%1, %2};" : "=l"(r) : "f"(lo), "f"(hi)); return r;
}
__device__ __forceinline__ float2 unpack2(u64 v) {
    float2 f; asm("mov.b64 {%0, %1}, %2;" : "=f"(f.x), "=f"(f.y) : "l"(v)); return f;
}

// ---------------- device scratch (no allocs allowed) ----------------
__device__ float g_xinner[TOT * H2n];  // up-proj output: [x_m | z]
__device__ float g_act   [TOT * Hn];   // silu(conv(x_m))
__device__ float g_q     [TOT * Hn];
__device__ float g_k     [TOT * Hn];
__device__ float g_v     [TOT * Hn];
__device__ float g_h     [TOT * Hn];   // mLSTM cell output
__device__ float g_hst   [TOT * Hn];   // post-LN/skip/gate
__device__ float g_ig    [Bn*NHn*Sn];
__device__ float g_lf    [Bn*NHn*Sn];  // logsigmoid(fg)
__device__ float g_a     [Bn*NHn*Sn];  // a_t = ig_t - c_t
__device__ float g_M     [Bn*NHn*Sn];  // running max of a
__device__ float g_nfl   [Bn*NHn*Sn];  // exp(-m_s)

// ---------------- tf32 helpers ----------------
__device__ __forceinline__ uint32_t f2tf32(float x) {
    uint32_t r;
    asm("cvt.rna.tf32.f32 %0, %1;" : "=r"(r) : "f"(x));
    return r;
}

__device__ __forceinline__ void mma_tf32(float* c, const uint32_t* a, const uint32_t* b) {
    asm volatile(
        "mma.sync.aligned.m16n8k8.row.col.f32.tf32.tf32.f32 "
        "{%0,%1,%2,%3}, {%4,%5,%6,%7}, {%8,%9}, {%0,%1,%2,%3};\n"
        : "+f"(c[0]), "+f"(c[1]), "+f"(c[2]), "+f"(c[3])
        : "r"(a[0]), "r"(a[1]), "r"(a[2]), "r"(a[3]), "r"(b[0]), "r"(b[1]));
}

// ---------------- tensor-core tf32 GEMM: C = A(MxK) @ B(KxN), row-major ----------------
#define ASTRIDE 20
#define BSTRIDE 136
__global__ __launch_bounds__(256) void mma_gemm_kernel(
    const float* __restrict__ A, const float* __restrict__ B,
    float* __restrict__ C, int M, int N, int K)
{
    __shared__ uint32_t As[2][128 * ASTRIDE];
    __shared__ uint32_t Bs[2][16 * BSTRIDE];

    int tid  = threadIdx.x;
    int lane = tid & 31, warp = tid >> 5;
    int wm = warp & 1, wn = warp >> 1;
    int bx = blockIdx.x, by = blockIdx.y;

    int ar  = tid & 127;
    int ach = tid >> 7;
    int br  = tid >> 4;
    int bc  = (tid & 15) * 8;

    const float* Ap = A + (size_t)(by * 128 + ar) * K + ach * 8;
    const float* Bp = B + (size_t)br * N + bx * 128 + bc;

    float acc[4][4][4];
    #pragma unroll
    for (int mt = 0; mt < 4; mt++)
        #pragma unroll
        for (int nt = 0; nt < 4; nt++)
            #pragma unroll
            for (int e = 0; e < 4; e++) acc[mt][nt][e] = 0.f;

    int nk = K >> 4;
    float4 ra0, ra1, rb0, rb1;

    ra0 = *(const float4*)(Ap);
    ra1 = *(const float4*)(Ap + 4);
    rb0 = *(const float4*)(Bp);
    rb1 = *(const float4*)(Bp + 4);
    {
        int ab = ar * ASTRIDE + ach * 8;
        As[0][ab + 0] = f2tf32(ra0.x); As[0][ab + 1] = f2tf32(ra0.y);
        As[0][ab + 2] = f2tf32(ra0.z); As[0][ab + 3] = f2tf32(ra0.w);
        As[0][ab + 4] = f2tf32(ra1.x); As[0][ab + 5] = f2tf32(ra1.y);
        As[0][ab + 6] = f2tf32(ra1.z); As[0][ab + 7] = f2tf32(ra1.w);
        int bb = br * BSTRIDE + bc;
        Bs[0][bb + 0] = f2tf32(rb0.x); Bs[0][bb + 1] = f2tf32(rb0.y);
        Bs[0][bb + 2] = f2tf32(rb0.z); Bs[0][bb + 3] = f2tf32(rb0.w);
        Bs[0][bb + 4] = f2tf32(rb1.x); Bs[0][bb + 5] = f2tf32(rb1.y);
        Bs[0][bb + 6] = f2tf32(rb1.z); Bs[0][bb + 7] = f2tf32(rb1.w);
    }
    __syncthreads();

    int p = 0;
    for (int k0 = 0; k0 < nk; k0++) {
        if (k0 + 1 < nk) {
            const float* An = Ap + (size_t)(k0 + 1) * 16;
            const float* Bnp = Bp + (size_t)(k0 + 1) * 16 * N;
            ra0 = *(const float4*)(An);
            ra1 = *(const float4*)(An + 4);
            rb0 = *(const float4*)(Bnp);
            rb1 = *(const float4*)(Bnp + 4);
        }
        #pragma unroll
        for (int h = 0; h < 2; h++) {
            int kb = h * 8 + (lane & 3);
            uint32_t af[4][4], bf[4][2];
            #pragma unroll
            for (int mt = 0; mt < 4; mt++) {
                int m = wm * 64 + mt * 16 + (lane >> 2);
                af[mt][0] = As[p][m * ASTRIDE + kb];
                af[mt][1] = As[p][(m + 8) * ASTRIDE + kb];
                af[mt][2] = As[p][m * ASTRIDE + kb + 4];
                af[mt][3] = As[p][(m + 8) * ASTRIDE + kb + 4];
            }
            #pragma unroll
            for (int nt = 0; nt < 4; nt++) {
                int n = wn * 32 + nt * 8 + (lane >> 2);
                bf[nt][0] = Bs[p][kb * BSTRIDE + n];
                bf[nt][1] = Bs[p][(kb + 4) * BSTRIDE + n];
            }
            #pragma unroll
            for (int mt = 0; mt < 4; mt++)
                #pragma unroll
                for (int nt = 0; nt < 4; nt++)
                    mma_tf32(acc[mt][nt], af[mt], bf[nt]);
        }
        if (k0 + 1 < nk) {
            int q = p ^ 1;
            int ab = ar * ASTRIDE + ach * 8;
            As[q][ab + 0] = f2tf32(ra0.x); As[q][ab + 1] = f2tf32(ra0.y);
            As[q][ab + 2] = f2tf32(ra0.z); As[q][ab + 3] = f2tf32(ra0.w);
            As[q][ab + 4] = f2tf32(ra1.x); As[q][ab + 5] = f2tf32(ra1.y);
            As[q][ab + 6] = f2tf32(ra1.z); As[q][ab + 7] = f2tf32(ra1.w);
            int bb = br * BSTRIDE + bc;
            Bs[q][bb + 0] = f2tf32(rb0.x); Bs[q][bb + 1] = f2tf32(rb0.y);
            Bs[q][bb + 2] = f2tf32(rb0.z); Bs[q][bb + 3] = f2tf32(rb0.w);
            Bs[q][bb + 4] = f2tf32(rb1.x); Bs[q][bb + 5] = f2tf32(rb1.y);
            Bs[q][bb + 6] = f2tf32(rb1.z); Bs[q][bb + 7] = f2tf32(rb1.w);
            __syncthreads();
            p = q;
        }
    }

    #pragma unroll
    for (int mt = 0; mt < 4; mt++) {
        int row = by * 128 + wm * 64 + mt * 16 + (lane >> 2);
        #pragma unroll
        for (int nt = 0; nt < 4; nt++) {
            int col = bx * 128 + wn * 32 + nt * 8 + 2 * (lane & 3);
            float2 v0 = make_float2(acc[mt][nt][0], acc[mt][nt][1]);
            float2 v1 = make_float2(acc[mt][nt][2], acc[mt][nt][3]);
            *(float2*)&C[(size_t)row * N + col] = v0;
            *(float2*)&C[(size_t)(row + 8) * N + col] = v1;
        }
    }
}

// ---------------- fused: causal conv(K=4) + bias + SiLU + headwise qkv ----------------
// one thread per (row p, 4-dim head block)
__global__ void conv_head_kernel(const float* __restrict__ conv_k,
                                 const float* __restrict__ conv_b,
                                 const float* __restrict__ Wq,
                                 const float* __restrict__ Wk,
                                 const float* __restrict__ Wv) {
    int idx = blockIdx.x * blockDim.x + threadIdx.x;
    if (idx >= TOT * NPH) return;
    int head = idx % NPH;
    int p = idx / NPH;
    int s = p % Sn;
    int h4 = head * 4;

    float4 bv = *(const float4*)&conv_b[h4];
    float a[4] = {bv.x, bv.y, bv.z, bv.w};
    float xv[4];
    #pragma unroll
    for (int j = 0; j < 4; j++) {
        int t = s - 3 + j;
        if (t >= 0) {
            float4 xm = *(const float4*)&g_xinner[(size_t)(p - s + t) * H2n + h4];
            float4 w  = *(const float4*)&conv_k[j * Hn + h4];
            a[0] += xm.x * w.x; a[1] += xm.y * w.y;
            a[2] += xm.z * w.z; a[3] += xm.w * w.w;
            if (j == 3) { xv[0] = xm.x; xv[1] = xm.y; xv[2] = xm.z; xv[3] = xm.w; }
        }
    }
    // SiLU
    #pragma unroll
    for (int u = 0; u < 4; u++) a[u] = a[u] / (1.f + expf(-a[u]));
    *(float4*)&g_act[(size_t)p * Hn + h4] = make_float4(a[0], a[1], a[2], a[3]);

    float q[4] = {0, 0, 0, 0}, k[4] = {0, 0, 0, 0}, v[4] = {0, 0, 0, 0};
    #pragma unroll
    for (int d = 0; d < 4; d++) {
        float4 wq = *(const float4*)&Wq[head * 16 + d * 4];
        float4 wk = *(const float4*)&Wk[head * 16 + d * 4];
        float4 wv = *(const float4*)&Wv[head * 16 + d * 4];
        q[0] += a[d] * wq.x; q[1] += a[d] * wq.y; q[2] += a[d] * wq.z; q[3] += a[d] * wq.w;
        k[0] += a[d] * wk.x; k[1] += a[d] * wk.y; k[2] += a[d] * wk.z; k[3] += a[d] * wk.w;
        v[0] += xv[d] * wv.x; v[1] += xv[d] * wv.y; v[2] += xv[d] * wv.z; v[3] += xv[d] * wv.w;
    }
    *(float4*)&g_q[(size_t)p * Hn + h4] = make_float4(q[0], q[1], q[2], q[3]);
    *(float4*)&g_k[(size_t)p * Hn + h4] = make_float4(k[0], k[1], k[2], k[3]);
    *(float4*)&g_v[(size_t)p * Hn + h4] = make_float4(v[0], v[1], v[2], v[3]);
}

// ---------------- input/forget gate projections ----------------
#define GR 4
__global__ void gates_kernel(const float* __restrict__ W_ig,
                             const float* __restrict__ b_ig,
                             const float* __restrict__ W_fg,
                             const float* __restrict__ b_fg) {
    int p0 = blockIdx.x * GR;
    int tid = threadIdx.x;       // 256
    int lane = tid & 31, warp = tid >> 5;
    float acc[GR][8];
    #pragma unroll
    for (int r = 0; r < GR; r++)
        #pragma unroll
        for (int v = 0; v < 8; v++) acc[r][v] = 0.f;

    const float4* wig4 = (const float4*)W_ig;
    const float4* wfg4 = (const float4*)W_fg;
    for (int i = tid; i < 3 * Hn; i += 256) {
        float4 wi = wig4[i];
        float4 wf = wfg4[i];
        const float* src;
        int off;
        if (i < Hn)          { src = g_q; off = i; }
        else if (i < 2 * Hn) { src = g_k; off = i - Hn; }
        else                 { src = g_v; off = i - 2 * Hn; }
        #pragma unroll
        for (int r = 0; r < GR; r++) {
            float g = src[(size_t)(p0 + r) * Hn + off];
            acc[r][0] += g * wi.x; acc[r][1] += g * wi.y;
            acc[r][2] += g * wi.z; acc[r][3] += g * wi.w;
            acc[r][4] += g * wf.x; acc[r][5] += g * wf.y;
            acc[r][6] += g * wf.z; acc[r][7] += g * wf.w;
        }
    }
    #pragma unroll
    for (int r = 0; r < GR; r++)
        #pragma unroll
        for (int v = 0; v < 8; v++)
            #pragma unroll
            for (int o = 16; o > 0; o >>= 1)
                acc[r][v] += __shfl_down_sync(0xffffffffu, acc[r][v], o);
    __shared__ float sred[8][32];
    if (lane == 0) {
        #pragma unroll
        for (int r = 0; r < GR; r++)
            #pragma unroll
            for (int v = 0; v < 8; v++)
                sred[warp][r * 8 + v] = acc[r][v];
    }
    __syncthreads();
    if (tid < 32) {
        float s = 0.f;
        #pragma unroll
        for (int w = 0; w < 8; w++) s += sred[w][tid];
        int r = tid >> 3, gsel = tid & 7;
        int pp = p0 + r;
        int b = pp / Sn, ss = pp % Sn;
        int n = gsel & 3;
        int o = (b * NHn + n) * Sn + ss;
        if (gsel < 4) {
            g_ig[o] = s + b_ig[n];
        } else {
            float fgv = s + b_fg[n];
            g_lf[o] = fminf(fgv, 0.f) - log1pf(expf(-fabsf(fgv)));
        }
    }
}

// ---------------- parallel scan per (b,n) ----------------
__global__ void scan_kernel() {
    __shared__ float sc[256];
    int bn = blockIdx.x;
    int tid = threadIdx.x;
    int off = bn * Sn + tid * 8;

    float locc[8];
    float run = 0.f;
    #pragma unroll
    for (int j = 0; j < 8; j++) { run += g_lf[off + j]; locc[j] = run; }

    sc[tid] = run;
    __syncthreads();
    for (int d = 1; d < 256; d <<= 1) {
        float add = (tid >= d) ? sc[tid - d] : 0.f;
        __syncthreads();
        sc[tid] += add;
        __syncthreads();
    }
    float coff = sc[tid] - run;

    float av[8];
    float rmax = -INFINITY;
    #pragma unroll
    for (int j = 0; j < 8; j++) {
        locc[j] += coff;
        av[j] = g_ig[off + j] - locc[j];
        rmax = fmaxf(rmax, av[j]);
    }
    __syncthreads();

    sc[tid] = rmax;
    __syncthreads();
    for (int d = 1; d < 256; d <<= 1) {
        float m = (tid >= d) ? sc[tid - d] : -INFINITY;
        __syncthreads();
        sc[tid] = fmaxf(sc[tid], m);
        __syncthreads();
    }
    float Mr = (tid == 0) ? -INFINITY : sc[tid - 1];

    #pragma unroll
    for (int j = 0; j < 8; j++) {
        Mr = fmaxf(Mr, av[j]);
        g_a[off + j] = av[j];
        g_M[off + j] = Mr;
        g_nfl[off + j] = expf(-(locc[j] + Mr));
    }
}

// ---------------- tiled mLSTM cell (FFMA2 packed-fp32) ----------------
// grid: (NQT, B*NH), 256 threads, ~194 KB dynamic smem.
// thread (tx,ty): queries ty*4..+3, keys {tx+16j}, dim-pairs {tx+16j}
__global__ __launch_bounds__(256) void attn_tiled_kernel() {
    extern __shared__ float smem[];
    float* sQ   = smem + SM_Q;     // [TQ][DHP]
    float* sVf  = smem + SM_KV;    // V: [TK][DHP] floats (union with sK2)
    u64*   sK2  = (u64*)(smem + SM_KV);  // K dim-pairs: [DH2][TKP2] u64
    float* sW   = smem + SM_W;     // [TQ][TKP]
    float* sM   = smem + SM_M;
    float* sSum = smem + SM_SUM;
    float* sA   = smem + SM_A;

    int bn = blockIdx.y;
    int n = bn % NHn, b = bn / NHn;
    int qt = (NQT - 1) - blockIdx.x;   // longest blocks first
    int q0 = qt * TQ;
    int tid = threadIdx.x;
    int tx = tid & 15, ty = tid >> 4;
    int abase = bn * Sn;

    for (int i = tid; i < TQ * DH4; i += 256) {
        int r = i / DH4, c = i % DH4;
        ((float4*)(sQ + r * DHP))[c] =
            ((const float4*)&g_q[(size_t)(b * Sn + q0 + r) * Hn + n * DHn])[c];
    }
    if (tid < TQ) {
        sM[tid] = g_M[abase + q0 + tid];
        sSum[tid] = 0.f;
    }
    __syncthreads();

    // accumulators: 4 queries x 11 dim-pairs (pair index = tx + 16*j)
    u64 acc2[4][11];
    #pragma unroll
    for (int i = 0; i < 4; i++)
        #pragma unroll
        for (int j = 0; j < 11; j++) acc2[i][j] = 0ull;

    const float scale = rsqrtf((float)DHn);
    int nkt = qt + 1;

    for (int kt = 0; kt < nkt; kt++) {
        int k0 = kt * TK;
        __syncthreads();   // previous V reads done before overwriting union buffer
        // stage K as dim-pair-transposed u64: sK2[pair][key]
        for (int i = tid; i < TK * DH4; i += 256) {
            int r = i / DH4, c = i % DH4;
            float4 kq = ((const float4*)&g_k[(size_t)(b * Sn + k0 + r) * Hn + n * DHn])[c];
            sK2[(2 * c    ) * TKP2 + r] = pack2(kq.x, kq.y);
            sK2[(2 * c + 1) * TKP2 + r] = pack2(kq.z, kq.w);
        }
        if (tid < TK) sA[tid] = g_a[abase + k0 + tid];
        __syncthreads();

        // QK^T: 4 queries x 4 keys (keys tx+16j), packed dim pairs
        u64 w2[4][4];
        #pragma unroll
        for (int i = 0; i < 4; i++)
            #pragma unroll
            for (int j = 0; j < 4; j++) w2[i][j] = 0ull;

        #pragma unroll 2
        for (int c = 0; c < DH4; c++) {
            ulonglong2 qv[4];
            #pragma unroll
            for (int i = 0; i < 4; i++)
                qv[i] = *(const ulonglong2*)(sQ + (ty * 4 + i) * DHP + 4 * c);
            u64 ka[4], kb[4];
            #pragma unroll
            for (int j = 0; j < 4; j++) {
                int key = tx + 16 * j;
                ka[j] = sK2[(2 * c    ) * TKP2 + key];
                kb[j] = sK2[(2 * c + 1) * TKP2 + key];
            }
            #pragma unroll
            for (int i = 0; i < 4; i++)
                #pragma unroll
                for (int j = 0; j < 4; j++) {
                    ffma2(w2[i][j], qv[i].x, ka[j]);
                    ffma2(w2[i][j], qv[i].y, kb[j]);
                }
        }

        // finalize: mask, scale, exp; store to sW; row sums
        float rsum[4];
        #pragma unroll
        for (int i = 0; i < 4; i++) {
            int q = q0 + ty * 4 + i;
            float Ms = sM[ty * 4 + i];
            rsum[i] = 0.f;
            #pragma unroll
            for (int j = 0; j < 4; j++) {
                int t = k0 + tx + 16 * j;
                float2 pr = unpack2(w2[i][j]);
                float val = (t <= q)
                    ? (pr.x + pr.y) * scale * __expf(sA[tx + 16 * j] - Ms) : 0.f;
                sW[(ty * 4 + i) * TKP + tx + 16 * j] = val;
                rsum[i] += val;
            }
        }
        #pragma unroll
        for (int o = 8; o > 0; o >>= 1)
            #pragma unroll
            for (int i = 0; i < 4; i++)
                rsum[i] += __shfl_down_sync(0xffffffffu, rsum[i], o, 16);
        if (tx == 0) {
            #pragma unroll
            for (int i = 0; i < 4; i++) sSum[ty * 4 + i] += rsum[i];
        }
        __syncthreads();   // sW ready; QK done with sK2

        // stage V row-major
        for (int i = tid; i < TK * DH4; i += 256) {
            int r = i / DH4, c = i % DH4;
            ((float4*)(sVf + r * DHP))[c] =
                ((const float4*)&g_v[(size_t)(b * Sn + k0 + r) * Hn + n * DHn])[c];
        }
        __syncthreads();

        // PV: acc2[q][pair] += w[q][t] * v2[t][pair]
        const u64* sV2 = (const u64*)sVf;
        #pragma unroll 1
        for (int t4 = 0; t4 < TK / 4; t4++) {
            float4 wv[4];
            #pragma unroll
            for (int i = 0; i < 4; i++)
                wv[i] = *(const float4*)&sW[(ty * 4 + i) * TKP + t4 * 4];
            #pragma unroll
            for (int u = 0; u < 4; u++) {
                int t = t4 * 4 + u;
                u64 wb[4];
                wb[0] = pack2((&wv[0].x)[u], (&wv[0].x)[u]);
                wb[1] = pack2((&wv[1].x)[u], (&wv[1].x)[u]);
                wb[2] = pack2((&wv[2].x)[u], (&wv[2].x)[u]);
                wb[3] = pack2((&wv[3].x)[u], (&wv[3].x)[u]);
                const u64* vrow = sV2 + (size_t)t * DHP2;
                #pragma unroll
                for (int j = 0; j < 10; j++) {
                    u64 vv = vrow[tx + 16 * j];
                    ffma2(acc2[0][j], wb[0], vv);
                    ffma2(acc2[1][j], wb[1], vv);
                    ffma2(acc2[2][j], wb[2], vv);
                    ffma2(acc2[3][j], wb[3], vv);
                }
                if (tx < 8) {
                    u64 vv = vrow[tx + 160];
                    ffma2(acc2[0][10], wb[0], vv);
                    ffma2(acc2[1][10], wb[1], vv);
                    ffma2(acc2[2][10], wb[2], vv);
                    ffma2(acc2[3][10], wb[3], vv);
                }
            }
        }
    }
    __syncthreads();

    // epilogue: normalize and store (dims 2*(tx+16j), +1)
    #pragma unroll
    for (int i = 0; i < 4; i++) {
        int q = ty * 4 + i;
        float s = sSum[q];
        float nfl = g_nfl[abase + q0 + q];
        float inv = 1.f / (fmaxf(fabsf(s), nfl) + 1e-6f);
        float* orow = &g_h[(size_t)(b * Sn + q0 + q) * Hn + n * DHn];
        #pragma unroll
        for (int j = 0; j < 10; j++) {
            float2 h2 = unpack2(acc2[i][j]);
            *(float2*)&orow[2 * (tx + 16 * j)] = make_float2(h2.x * inv, h2.y * inv);
        }
        if (tx < 8) {
            float2 h2 = unpack2(acc2[i][10]);
            *(float2*)&orow[2 * (tx + 160)] = make_float2(h2.x * inv, h2.y * inv);
        }
    }
}

// ---------------- per-head LN + skip + SiLU(z) gate ----------------
__global__ void ln_gate_kernel(const float* __restrict__ ln_w,
                               const float* __restrict__ skip) {
    int rid = blockIdx.x;
    int p = rid >> 2;
    int n = rid & 3;
    int tid = threadIdx.x;         // 128
    const float* hrow = &g_h[(size_t)p * Hn + n * DHn];

    float sum = 0.f, sq = 0.f;
    for (int d = tid; d < DHn; d += 128) {
        float v = hrow[d];
        sum += v; sq += v * v;
    }
    __shared__ float s1[4], s2[4], sbc[2];
    #pragma unroll
    for (int o = 16; o > 0; o >>= 1) {
        sum += __shfl_down_sync(0xffffffffu, sum, o);
        sq  += __shfl_down_sync(0xffffffffu, sq, o);
    }
    if ((tid & 31) == 0) { s1[tid >> 5] = sum; s2[tid >> 5] = sq; }
    __syncthreads();
    if (tid == 0) {
        float ts = s1[0] + s1[1] + s1[2] + s1[3];
        float tq = s2[0] + s2[1] + s2[2] + s2[3];
        float mu = ts / (float)DHn;
        float var = fmaxf(tq / (float)DHn - mu * mu, 0.f);
        sbc[0] = mu;
        sbc[1] = rsqrtf(var + 1e-5f);
    }
    __syncthreads();
    float mu = sbc[0], rs = sbc[1];
    for (int d = tid; d < DHn; d += 128) {
        int hidx = n * DHn + d;
        float hnv = (hrow[d] - mu) * rs * ln_w[hidx];
        float z = g_xinner[(size_t)p * H2n + Hn + hidx];
        float sz = z / (1.f + expf(-z));
        g_hst[(size_t)p * Hn + hidx] = (hnv + skip[hidx] * g_act[(size_t)p * Hn + hidx]) * sz;
    }
}

// ---------------- launch ----------------
extern "C" void kernel_launch(void* const* d_in, const int* in_sizes, int n_in,
                              void* d_out, int out_size) {
    const float* x      = (const float*)d_in[0];
    const float* W_up   = (const float*)d_in[1];
    const float* conv_k = (const float*)d_in[2];
    const float* conv_b = (const float*)d_in[3];
    const float* Wq     = (const float*)d_in[4];
    const float* Wk     = (const float*)d_in[5];
    const float* Wv     = (const float*)d_in[6];
    const float* W_ig   = (const float*)d_in[7];
    const float* b_ig   = (const float*)d_in[8];
    const float* W_fg   = (const float*)d_in[9];
    const float* b_fg   = (const float*)d_in[10];
    const float* ln_w   = (const float*)d_in[11];
    const float* skip   = (const float*)d_in[12];
    const float* W_down = (const float*)d_in[13];
    float* out = (float*)d_out;

    void *p_xinner = nullptr, *p_hst = nullptr;
    cudaGetSymbolAddress(&p_xinner, g_xinner);
    cudaGetSymbolAddress(&p_hst, g_hst);

    static bool attr_set = false;
    if (!attr_set) {
        cudaFuncSetAttribute(attn_tiled_kernel,
                             cudaFuncAttributeMaxDynamicSharedMemorySize,
                             ATTN_SMEM_BYTES);
        attr_set = true;
    }

    // 1. up projection: (4096x1024) @ (1024x2688) — tf32 tensor cores
    mma_gemm_kernel<<<dim3(H2n / 128, TOT / 128), 256>>>(x, W_up, (float*)p_xinner,
                                                         TOT, H2n, En);
    // 2. fused conv + SiLU + headwise qkv
    {
        int nthr = TOT * NPH;
        conv_head_kernel<<<(nthr + 255) / 256, 256>>>(conv_k, conv_b, Wq, Wk, Wv);
    }
    // 3. gate projections
    gates_kernel<<<TOT / GR, 256>>>(W_ig, b_ig, W_fg, b_fg);
    // 4. per-(b,n) parallel scan
    scan_kernel<<<Bn * NHn, 256>>>();
    // 5. tiled mLSTM cell (FFMA2)
    attn_tiled_kernel<<<dim3(NQT, Bn * NHn), 256, ATTN_SMEM_BYTES>>>();
    // 6. multi-head LN + skip + SiLU(z) gate
    ln_gate_kernel<<<TOT * NHn, 128>>>(ln_w, skip);
    // 7. down projection: (4096x1344) @ (1344x1024) — tf32 tensor cores
    mma_gemm_kernel<<<dim3(En / 128, TOT / 128), 256>>>((const float*)p_hst, W_down,
                                                        out, TOT, En, Hn);
}

// round 11
// speedup vs baseline: 6.8845x; 1.5194x over previous
#include <cuda_runtime.h>
#include <math.h>
#include <stdint.h>

// ---------------- problem constants ----------------
#define Bn   2
#define Sn   2048
#define En   1024
#define Hn   1344
#define H2n  2688
#define NHn  4
#define DHn  336
#define DH4  84           // DHn/4
#define NPH  (Hn/4)       // 336 projection heads
#define TOT  (Bn*Sn)      // 4096 rows

// attention tiling (tensor-core version)
#define TQ   64
#define TK   64
#define SKS  340          // u32 row stride for Q/K/V tf32 tiles (340%32=20 -> conflict-free)
#define WS   68           // u32 row stride for W tile (68%32=4 -> conflict-free A-frags)
#define NQT  (Sn/TQ)      // 32

// smem layout (u32 units)
#define USM_Q   0
#define USM_KV  (TQ*SKS)                    // 21760
#define USM_W   (USM_KV + TK*SKS)           // 43520
#define USM_M   (USM_W + TQ*WS)             // 47872
#define USM_A   (USM_M + TQ)
#define USM_SUM (USM_A + TK)
#define USM_TOT (USM_SUM + TQ)
#define ATTN_SMEM_BYTES (USM_TOT * 4)       // 192,256 B

// ---------------- device scratch (no allocs allowed) ----------------
__device__ float g_xinner[TOT * H2n];  // up-proj output: [x_m | z]
__device__ float g_act   [TOT * Hn];   // silu(conv(x_m))
__device__ float g_q     [TOT * Hn];
__device__ float g_k     [TOT * Hn];
__device__ float g_v     [TOT * Hn];
__device__ float g_h     [TOT * Hn];   // mLSTM cell output
__device__ float g_hst   [TOT * Hn];   // post-LN/skip/gate
__device__ float g_ig    [Bn*NHn*Sn];
__device__ float g_lf    [Bn*NHn*Sn];  // logsigmoid(fg)
__device__ float g_a     [Bn*NHn*Sn];  // a_t = ig_t - c_t
__device__ float g_M     [Bn*NHn*Sn];  // running max of a
__device__ float g_nfl   [Bn*NHn*Sn];  // exp(-m_s)

// ---------------- tf32 helpers ----------------
__device__ __forceinline__ uint32_t f2tf32(float x) {
    uint32_t r;
    asm("cvt.rna.tf32.f32 %0, %1;" : "=r"(r) : "f"(x));
    return r;
}

__device__ __forceinline__ void mma_tf32(float* c, const uint32_t* a, const uint32_t* b) {
    asm volatile(
        "mma.sync.aligned.m16n8k8.row.col.f32.tf32.tf32.f32 "
        "{%0,%1,%2,%3}, {%4,%5,%6,%7}, {%8,%9}, {%0,%1,%2,%3};\n"
        : "+f"(c[0]), "+f"(c[1]), "+f"(c[2]), "+f"(c[3])
        : "r"(a[0]), "r"(a[1]), "r"(a[2]), "r"(a[3]), "r"(b[0]), "r"(b[1]));
}

// ---------------- tensor-core tf32 GEMM: C = A(MxK) @ B(KxN), row-major ----------------
#define ASTRIDE 20
#define BSTRIDE 136
__global__ __launch_bounds__(256) void mma_gemm_kernel(
    const float* __restrict__ A, const float* __restrict__ B,
    float* __restrict__ C, int M, int N, int K)
{
    __shared__ uint32_t As[2][128 * ASTRIDE];
    __shared__ uint32_t Bs[2][16 * BSTRIDE];

    int tid  = threadIdx.x;
    int lane = tid & 31, warp = tid >> 5;
    int wm = warp & 1, wn = warp >> 1;
    int bx = blockIdx.x, by = blockIdx.y;

    int ar  = tid & 127;
    int ach = tid >> 7;
    int br  = tid >> 4;
    int bc  = (tid & 15) * 8;

    const float* Ap = A + (size_t)(by * 128 + ar) * K + ach * 8;
    const float* Bp = B + (size_t)br * N + bx * 128 + bc;

    float acc[4][4][4];
    #pragma unroll
    for (int mt = 0; mt < 4; mt++)
        #pragma unroll
        for (int nt = 0; nt < 4; nt++)
            #pragma unroll
            for (int e = 0; e < 4; e++) acc[mt][nt][e] = 0.f;

    int nk = K >> 4;
    float4 ra0, ra1, rb0, rb1;

    ra0 = *(const float4*)(Ap);
    ra1 = *(const float4*)(Ap + 4);
    rb0 = *(const float4*)(Bp);
    rb1 = *(const float4*)(Bp + 4);
    {
        int ab = ar * ASTRIDE + ach * 8;
        As[0][ab + 0] = f2tf32(ra0.x); As[0][ab + 1] = f2tf32(ra0.y);
        As[0][ab + 2] = f2tf32(ra0.z); As[0][ab + 3] = f2tf32(ra0.w);
        As[0][ab + 4] = f2tf32(ra1.x); As[0][ab + 5] = f2tf32(ra1.y);
        As[0][ab + 6] = f2tf32(ra1.z); As[0][ab + 7] = f2tf32(ra1.w);
        int bb = br * BSTRIDE + bc;
        Bs[0][bb + 0] = f2tf32(rb0.x); Bs[0][bb + 1] = f2tf32(rb0.y);
        Bs[0][bb + 2] = f2tf32(rb0.z); Bs[0][bb + 3] = f2tf32(rb0.w);
        Bs[0][bb + 4] = f2tf32(rb1.x); Bs[0][bb + 5] = f2tf32(rb1.y);
        Bs[0][bb + 6] = f2tf32(rb1.z); Bs[0][bb + 7] = f2tf32(rb1.w);
    }
    __syncthreads();

    int p = 0;
    for (int k0 = 0; k0 < nk; k0++) {
        if (k0 + 1 < nk) {
            const float* An = Ap + (size_t)(k0 + 1) * 16;
            const float* Bnp = Bp + (size_t)(k0 + 1) * 16 * N;
            ra0 = *(const float4*)(An);
            ra1 = *(const float4*)(An + 4);
            rb0 = *(const float4*)(Bnp);
            rb1 = *(const float4*)(Bnp + 4);
        }
        #pragma unroll
        for (int h = 0; h < 2; h++) {
            int kb = h * 8 + (lane & 3);
            uint32_t af[4][4], bf[4][2];
            #pragma unroll
            for (int mt = 0; mt < 4; mt++) {
                int m = wm * 64 + mt * 16 + (lane >> 2);
                af[mt][0] = As[p][m * ASTRIDE + kb];
                af[mt][1] = As[p][(m + 8) * ASTRIDE + kb];
                af[mt][2] = As[p][m * ASTRIDE + kb + 4];
                af[mt][3] = As[p][(m + 8) * ASTRIDE + kb + 4];
            }
            #pragma unroll
            for (int nt = 0; nt < 4; nt++) {
                int n = wn * 32 + nt * 8 + (lane >> 2);
                bf[nt][0] = Bs[p][kb * BSTRIDE + n];
                bf[nt][1] = Bs[p][(kb + 4) * BSTRIDE + n];
            }
            #pragma unroll
            for (int mt = 0; mt < 4; mt++)
                #pragma unroll
                for (int nt = 0; nt < 4; nt++)
                    mma_tf32(acc[mt][nt], af[mt], bf[nt]);
        }
        if (k0 + 1 < nk) {
            int q = p ^ 1;
            int ab = ar * ASTRIDE + ach * 8;
            As[q][ab + 0] = f2tf32(ra0.x); As[q][ab + 1] = f2tf32(ra0.y);
            As[q][ab + 2] = f2tf32(ra0.z); As[q][ab + 3] = f2tf32(ra0.w);
            As[q][ab + 4] = f2tf32(ra1.x); As[q][ab + 5] = f2tf32(ra1.y);
            As[q][ab + 6] = f2tf32(ra1.z); As[q][ab + 7] = f2tf32(ra1.w);
            int bb = br * BSTRIDE + bc;
            Bs[q][bb + 0] = f2tf32(rb0.x); Bs[q][bb + 1] = f2tf32(rb0.y);
            Bs[q][bb + 2] = f2tf32(rb0.z); Bs[q][bb + 3] = f2tf32(rb0.w);
            Bs[q][bb + 4] = f2tf32(rb1.x); Bs[q][bb + 5] = f2tf32(rb1.y);
            Bs[q][bb + 6] = f2tf32(rb1.z); Bs[q][bb + 7] = f2tf32(rb1.w);
            __syncthreads();
            p = q;
        }
    }

    #pragma unroll
    for (int mt = 0; mt < 4; mt++) {
        int row = by * 128 + wm * 64 + mt * 16 + (lane >> 2);
        #pragma unroll
        for (int nt = 0; nt < 4; nt++) {
            int col = bx * 128 + wn * 32 + nt * 8 + 2 * (lane & 3);
            float2 v0 = make_float2(acc[mt][nt][0], acc[mt][nt][1]);
            float2 v1 = make_float2(acc[mt][nt][2], acc[mt][nt][3]);
            *(float2*)&C[(size_t)row * N + col] = v0;
            *(float2*)&C[(size_t)(row + 8) * N + col] = v1;
        }
    }
}

// ---------------- fused: causal conv(K=4) + bias + SiLU + headwise qkv ----------------
__global__ void conv_head_kernel(const float* __restrict__ conv_k,
                                 const float* __restrict__ conv_b,
                                 const float* __restrict__ Wq,
                                 const float* __restrict__ Wk,
                                 const float* __restrict__ Wv) {
    int idx = blockIdx.x * blockDim.x + threadIdx.x;
    if (idx >= TOT * NPH) return;
    int head = idx % NPH;
    int p = idx / NPH;
    int s = p % Sn;
    int h4 = head * 4;

    float4 bv = *(const float4*)&conv_b[h4];
    float a[4] = {bv.x, bv.y, bv.z, bv.w};
    float xv[4];
    #pragma unroll
    for (int j = 0; j < 4; j++) {
        int t = s - 3 + j;
        if (t >= 0) {
            float4 xm = *(const float4*)&g_xinner[(size_t)(p - s + t) * H2n + h4];
            float4 w  = *(const float4*)&conv_k[j * Hn + h4];
            a[0] += xm.x * w.x; a[1] += xm.y * w.y;
            a[2] += xm.z * w.z; a[3] += xm.w * w.w;
            if (j == 3) { xv[0] = xm.x; xv[1] = xm.y; xv[2] = xm.z; xv[3] = xm.w; }
        }
    }
    #pragma unroll
    for (int u = 0; u < 4; u++) a[u] = a[u] / (1.f + expf(-a[u]));
    *(float4*)&g_act[(size_t)p * Hn + h4] = make_float4(a[0], a[1], a[2], a[3]);

    float q[4] = {0, 0, 0, 0}, k[4] = {0, 0, 0, 0}, v[4] = {0, 0, 0, 0};
    #pragma unroll
    for (int d = 0; d < 4; d++) {
        float4 wq = *(const float4*)&Wq[head * 16 + d * 4];
        float4 wk = *(const float4*)&Wk[head * 16 + d * 4];
        float4 wv = *(const float4*)&Wv[head * 16 + d * 4];
        q[0] += a[d] * wq.x; q[1] += a[d] * wq.y; q[2] += a[d] * wq.z; q[3] += a[d] * wq.w;
        k[0] += a[d] * wk.x; k[1] += a[d] * wk.y; k[2] += a[d] * wk.z; k[3] += a[d] * wk.w;
        v[0] += xv[d] * wv.x; v[1] += xv[d] * wv.y; v[2] += xv[d] * wv.z; v[3] += xv[d] * wv.w;
    }
    *(float4*)&g_q[(size_t)p * Hn + h4] = make_float4(q[0], q[1], q[2], q[3]);
    *(float4*)&g_k[(size_t)p * Hn + h4] = make_float4(k[0], k[1], k[2], k[3]);
    *(float4*)&g_v[(size_t)p * Hn + h4] = make_float4(v[0], v[1], v[2], v[3]);
}

// ---------------- input/forget gate projections ----------------
#define GR 4
__global__ void gates_kernel(const float* __restrict__ W_ig,
                             const float* __restrict__ b_ig,
                             const float* __restrict__ W_fg,
                             const float* __restrict__ b_fg) {
    int p0 = blockIdx.x * GR;
    int tid = threadIdx.x;       // 256
    int lane = tid & 31, warp = tid >> 5;
    float acc[GR][8];
    #pragma unroll
    for (int r = 0; r < GR; r++)
        #pragma unroll
        for (int v = 0; v < 8; v++) acc[r][v] = 0.f;

    const float4* wig4 = (const float4*)W_ig;
    const float4* wfg4 = (const float4*)W_fg;
    for (int i = tid; i < 3 * Hn; i += 256) {
        float4 wi = wig4[i];
        float4 wf = wfg4[i];
        const float* src;
        int off;
        if (i < Hn)          { src = g_q; off = i; }
        else if (i < 2 * Hn) { src = g_k; off = i - Hn; }
        else                 { src = g_v; off = i - 2 * Hn; }
        #pragma unroll
        for (int r = 0; r < GR; r++) {
            float g = src[(size_t)(p0 + r) * Hn + off];
            acc[r][0] += g * wi.x; acc[r][1] += g * wi.y;
            acc[r][2] += g * wi.z; acc[r][3] += g * wi.w;
            acc[r][4] += g * wf.x; acc[r][5] += g * wf.y;
            acc[r][6] += g * wf.z; acc[r][7] += g * wf.w;
        }
    }
    #pragma unroll
    for (int r = 0; r < GR; r++)
        #pragma unroll
        for (int v = 0; v < 8; v++)
            #pragma unroll
            for (int o = 16; o > 0; o >>= 1)
                acc[r][v] += __shfl_down_sync(0xffffffffu, acc[r][v], o);
    __shared__ float sred[8][32];
    if (lane == 0) {
        #pragma unroll
        for (int r = 0; r < GR; r++)
            #pragma unroll
            for (int v = 0; v < 8; v++)
                sred[warp][r * 8 + v] = acc[r][v];
    }
    __syncthreads();
    if (tid < 32) {
        float s = 0.f;
        #pragma unroll
        for (int w = 0; w < 8; w++) s += sred[w][tid];
        int r = tid >> 3, gsel = tid & 7;
        int pp = p0 + r;
        int b = pp / Sn, ss = pp % Sn;
        int n = gsel & 3;
        int o = (b * NHn + n) * Sn + ss;
        if (gsel < 4) {
            g_ig[o] = s + b_ig[n];
        } else {
            float fgv = s + b_fg[n];
            g_lf[o] = fminf(fgv, 0.f) - log1pf(expf(-fabsf(fgv)));
        }
    }
}

// ---------------- parallel scan per (b,n) ----------------
__global__ void scan_kernel() {
    __shared__ float sc[256];
    int bn = blockIdx.x;
    int tid = threadIdx.x;
    int off = bn * Sn + tid * 8;

    float locc[8];
    float run = 0.f;
    #pragma unroll
    for (int j = 0; j < 8; j++) { run += g_lf[off + j]; locc[j] = run; }

    sc[tid] = run;
    __syncthreads();
    for (int d = 1; d < 256; d <<= 1) {
        float add = (tid >= d) ? sc[tid - d] : 0.f;
        __syncthreads();
        sc[tid] += add;
        __syncthreads();
    }
    float coff = sc[tid] - run;

    float av[8];
    float rmax = -INFINITY;
    #pragma unroll
    for (int j = 0; j < 8; j++) {
        locc[j] += coff;
        av[j] = g_ig[off + j] - locc[j];
        rmax = fmaxf(rmax, av[j]);
    }
    __syncthreads();

    sc[tid] = rmax;
    __syncthreads();
    for (int d = 1; d < 256; d <<= 1) {
        float m = (tid >= d) ? sc[tid - d] : -INFINITY;
        __syncthreads();
        sc[tid] = fmaxf(sc[tid], m);
        __syncthreads();
    }
    float Mr = (tid == 0) ? -INFINITY : sc[tid - 1];

    #pragma unroll
    for (int j = 0; j < 8; j++) {
        Mr = fmaxf(Mr, av[j]);
        g_a[off + j] = av[j];
        g_M[off + j] = Mr;
        g_nfl[off + j] = expf(-(locc[j] + Mr));
    }
}

// ---------------- tensor-core tiled mLSTM cell ----------------
// grid: (NQT, B*NH), 256 threads = 8 warps (wm=warp>>1: 4 m16-rows; wn=warp&1: n halves).
// QK^T and P@V via mma.sync tf32; exp/mask/rowsum on C fragments in registers.
__global__ __launch_bounds__(256) void attn_mma_kernel() {
    extern __shared__ uint32_t us[];
    uint32_t* sQ  = us + USM_Q;    // [64][SKS] tf32
    uint32_t* sKV = us + USM_KV;   // [64][SKS] tf32 (K then V per k-tile)
    uint32_t* sW  = us + USM_W;    // [64][WS]  tf32 weights
    float* sM   = (float*)(us + USM_M);
    float* sA   = (float*)(us + USM_A);
    float* sSum = (float*)(us + USM_SUM);

    int bn = blockIdx.y;
    int n = bn % NHn, b = bn / NHn;
    int qt = (NQT - 1) - blockIdx.x;   // longest blocks first
    int q0 = qt * TQ;
    int tid = threadIdx.x;
    int lane = tid & 31, warp = tid >> 5;
    int wm = warp >> 1, wn = warp & 1;
    int abase = bn * Sn;

    // stage Q (cvt to tf32)
    for (int i = tid; i < TQ * DH4; i += 256) {
        int r = i / DH4, c = i % DH4;
        float4 v = ((const float4*)&g_q[(size_t)(b * Sn + q0 + r) * Hn + n * DHn])[c];
        uint4 t = make_uint4(f2tf32(v.x), f2tf32(v.y), f2tf32(v.z), f2tf32(v.w));
        *(uint4*)&sQ[r * SKS + 4 * c] = t;
    }
    if (tid < TQ) {
        sM[tid] = g_M[abase + q0 + tid];
        sSum[tid] = 0.f;
    }
    __syncthreads();

    int r0 = wm * 16 + (lane >> 2);       // this thread's first C row
    float Ms0 = sM[r0], Ms1 = sM[r0 + 8];
    const float scale = rsqrtf((float)DHn);

    // PV accumulators: rows {r0, r0+8}, cols wn*168 + nt*8 + 2*(lane&3) (+1)
    float acc[21][4];
    #pragma unroll
    for (int nt = 0; nt < 21; nt++)
        #pragma unroll
        for (int e = 0; e < 4; e++) acc[nt][e] = 0.f;

    int nkt = qt + 1;
    for (int kt = 0; kt < nkt; kt++) {
        int k0 = kt * TK;
        __syncthreads();   // prior PV finished with sKV/sW
        // stage K (cvt to tf32)
        for (int i = tid; i < TK * DH4; i += 256) {
            int r = i / DH4, c = i % DH4;
            float4 v = ((const float4*)&g_k[(size_t)(b * Sn + k0 + r) * Hn + n * DHn])[c];
            uint4 t = make_uint4(f2tf32(v.x), f2tf32(v.y), f2tf32(v.z), f2tf32(v.w));
            *(uint4*)&sKV[r * SKS + 4 * c] = t;
        }
        if (tid < TK) sA[tid] = g_a[abase + k0 + tid];
        __syncthreads();

        // ---- QK^T: warp computes rows [wm*16, +16), keys [wn*32, +32) ----
        float wacc[4][4];
        #pragma unroll
        for (int nt = 0; nt < 4; nt++)
            #pragma unroll
            for (int e = 0; e < 4; e++) wacc[nt][e] = 0.f;

        #pragma unroll 2
        for (int c8 = 0; c8 < 42; c8++) {
            int cb = c8 * 8 + (lane & 3);
            uint32_t af[4];
            af[0] = sQ[r0 * SKS + cb];
            af[1] = sQ[(r0 + 8) * SKS + cb];
            af[2] = sQ[r0 * SKS + cb + 4];
            af[3] = sQ[(r0 + 8) * SKS + cb + 4];
            #pragma unroll
            for (int nt = 0; nt < 4; nt++) {
                int nn = wn * 32 + nt * 8 + (lane >> 2);
                uint32_t bf[2];
                bf[0] = sKV[nn * SKS + cb];
                bf[1] = sKV[nn * SKS + cb + 4];
                mma_tf32(wacc[nt], af, bf);
            }
        }

        // ---- postprocess: mask, scale*exp, tf32-round to sW, row sums ----
        float rs0 = 0.f, rs1 = 0.f;
        #pragma unroll
        for (int nt = 0; nt < 4; nt++) {
            int c0 = wn * 32 + nt * 8 + 2 * (lane & 3);
            int t0 = k0 + c0;
            float ea0 = sA[c0], ea1 = sA[c0 + 1];
            float w00 = (t0     <= q0 + r0)     ? wacc[nt][0] * scale * __expf(ea0 - Ms0) : 0.f;
            float w01 = (t0 + 1 <= q0 + r0)     ? wacc[nt][1] * scale * __expf(ea1 - Ms0) : 0.f;
            float w10 = (t0     <= q0 + r0 + 8) ? wacc[nt][2] * scale * __expf(ea0 - Ms1) : 0.f;
            float w11 = (t0 + 1 <= q0 + r0 + 8) ? wacc[nt][3] * scale * __expf(ea1 - Ms1) : 0.f;
            uint32_t u00 = f2tf32(w00), u01 = f2tf32(w01);
            uint32_t u10 = f2tf32(w10), u11 = f2tf32(w11);
            sW[r0 * WS + c0]           = u00;
            sW[r0 * WS + c0 + 1]       = u01;
            sW[(r0 + 8) * WS + c0]     = u10;
            sW[(r0 + 8) * WS + c0 + 1] = u11;
            rs0 += __uint_as_float(u00) + __uint_as_float(u01);
            rs1 += __uint_as_float(u10) + __uint_as_float(u11);
        }
        rs0 += __shfl_xor_sync(0xffffffffu, rs0, 1);
        rs0 += __shfl_xor_sync(0xffffffffu, rs0, 2);
        rs1 += __shfl_xor_sync(0xffffffffu, rs1, 1);
        rs1 += __shfl_xor_sync(0xffffffffu, rs1, 2);
        if ((lane & 3) == 0) {
            atomicAdd(&sSum[r0], rs0);
            atomicAdd(&sSum[r0 + 8], rs1);
        }
        __syncthreads();   // sW complete; sKV free

        // stage V (cvt to tf32)
        for (int i = tid; i < TK * DH4; i += 256) {
            int r = i / DH4, c = i % DH4;
            float4 v = ((const float4*)&g_v[(size_t)(b * Sn + k0 + r) * Hn + n * DHn])[c];
            uint4 t = make_uint4(f2tf32(v.x), f2tf32(v.y), f2tf32(v.z), f2tf32(v.w));
            *(uint4*)&sKV[r * SKS + 4 * c] = t;
        }
        __syncthreads();

        // ---- PV: warp computes rows [wm*16, +16), dims [wn*168, +168) ----
        #pragma unroll
        for (int k8 = 0; k8 < 8; k8++) {
            int tb = k8 * 8 + (lane & 3);
            uint32_t af[4];
            af[0] = sW[r0 * WS + tb];
            af[1] = sW[(r0 + 8) * WS + tb];
            af[2] = sW[r0 * WS + tb + 4];
            af[3] = sW[(r0 + 8) * WS + tb + 4];
            #pragma unroll
            for (int nt = 0; nt < 21; nt++) {
                int d = wn * 168 + nt * 8 + (lane >> 2);
                uint32_t bf[2];
                bf[0] = sKV[tb * SKS + d];
                bf[1] = sKV[(tb + 4) * SKS + d];
                mma_tf32(acc[nt], af, bf);
            }
        }
    }
    __syncthreads();

    // ---- epilogue: normalize and store ----
    float s0 = sSum[r0], s1 = sSum[r0 + 8];
    float inv0 = 1.f / (fmaxf(fabsf(s0), g_nfl[abase + q0 + r0]) + 1e-6f);
    float inv1 = 1.f / (fmaxf(fabsf(s1), g_nfl[abase + q0 + r0 + 8]) + 1e-6f);
    float* orow0 = &g_h[(size_t)(b * Sn + q0 + r0) * Hn + n * DHn];
    float* orow1 = &g_h[(size_t)(b * Sn + q0 + r0 + 8) * Hn + n * DHn];
    #pragma unroll
    for (int nt = 0; nt < 21; nt++) {
        int d = wn * 168 + nt * 8 + 2 * (lane & 3);
        *(float2*)&orow0[d] = make_float2(acc[nt][0] * inv0, acc[nt][1] * inv0);
        *(float2*)&orow1[d] = make_float2(acc[nt][2] * inv1, acc[nt][3] * inv1);
    }
}

// ---------------- per-head LN + skip + SiLU(z) gate ----------------
__global__ void ln_gate_kernel(const float* __restrict__ ln_w,
                               const float* __restrict__ skip) {
    int rid = blockIdx.x;
    int p = rid >> 2;
    int n = rid & 3;
    int tid = threadIdx.x;         // 128
    const float* hrow = &g_h[(size_t)p * Hn + n * DHn];

    float sum = 0.f, sq = 0.f;
    for (int d = tid; d < DHn; d += 128) {
        float v = hrow[d];
        sum += v; sq += v * v;
    }
    __shared__ float s1[4], s2[4], sbc[2];
    #pragma unroll
    for (int o = 16; o > 0; o >>= 1) {
        sum += __shfl_down_sync(0xffffffffu, sum, o);
        sq  += __shfl_down_sync(0xffffffffu, sq, o);
    }
    if ((tid & 31) == 0) { s1[tid >> 5] = sum; s2[tid >> 5] = sq; }
    __syncthreads();
    if (tid == 0) {
        float ts = s1[0] + s1[1] + s1[2] + s1[3];
        float tq = s2[0] + s2[1] + s2[2] + s2[3];
        float mu = ts / (float)DHn;
        float var = fmaxf(tq / (float)DHn - mu * mu, 0.f);
        sbc[0] = mu;
        sbc[1] = rsqrtf(var + 1e-5f);
    }
    __syncthreads();
    float mu = sbc[0], rs = sbc[1];
    for (int d = tid; d < DHn; d += 128) {
        int hidx = n * DHn + d;
        float hnv = (hrow[d] - mu) * rs * ln_w[hidx];
        float z = g_xinner[(size_t)p * H2n + Hn + hidx];
        float sz = z / (1.f + expf(-z));
        g_hst[(size_t)p * Hn + hidx] = (hnv + skip[hidx] * g_act[(size_t)p * Hn + hidx]) * sz;
    }
}

// ---------------- launch ----------------
extern "C" void kernel_launch(void* const* d_in, const int* in_sizes, int n_in,
                              void* d_out, int out_size) {
    const float* x      = (const float*)d_in[0];
    const float* W_up   = (const float*)d_in[1];
    const float* conv_k = (const float*)d_in[2];
    const float* conv_b = (const float*)d_in[3];
    const float* Wq     = (const float*)d_in[4];
    const float* Wk     = (const float*)d_in[5];
    const float* Wv     = (const float*)d_in[6];
    const float* W_ig   = (const float*)d_in[7];
    const float* b_ig   = (const float*)d_in[8];
    const float* W_fg   = (const float*)d_in[9];
    const float* b_fg   = (const float*)d_in[10];
    const float* ln_w   = (const float*)d_in[11];
    const float* skip   = (const float*)d_in[12];
    const float* W_down = (const float*)d_in[13];
    float* out = (float*)d_out;

    void *p_xinner = nullptr, *p_hst = nullptr;
    cudaGetSymbolAddress(&p_xinner, g_xinner);
    cudaGetSymbolAddress(&p_hst, g_hst);

    static bool attr_set = false;
    if (!attr_set) {
        cudaFuncSetAttribute(attn_mma_kernel,
                             cudaFuncAttributeMaxDynamicSharedMemorySize,
                             ATTN_SMEM_BYTES);
        attr_set = true;
    }

    // 1. up projection: (4096x1024) @ (1024x2688) — tf32 tensor cores
    mma_gemm_kernel<<<dim3(H2n / 128, TOT / 128), 256>>>(x, W_up, (float*)p_xinner,
                                                         TOT, H2n, En);
    // 2. fused conv + SiLU + headwise qkv
    {
        int nthr = TOT * NPH;
        conv_head_kernel<<<(nthr + 255) / 256, 256>>>(conv_k, conv_b, Wq, Wk, Wv);
    }
    // 3. gate projections
    gates_kernel<<<TOT / GR, 256>>>(W_ig, b_ig, W_fg, b_fg);
    // 4. per-(b,n) parallel scan
    scan_kernel<<<Bn * NHn, 256>>>();
    // 5. tensor-core tiled mLSTM cell
    attn_mma_kernel<<<dim3(NQT, Bn * NHn), 256, ATTN_SMEM_BYTES>>>();
    // 6. multi-head LN + skip + SiLU(z) gate
    ln_gate_kernel<<<TOT * NHn, 128>>>(ln_w, skip);
    // 7. down projection: (4096x1344) @ (1344x1024) — tf32 tensor cores
    mma_gemm_kernel<<<dim3(En / 128, TOT / 128), 256>>>((const float*)p_hst, W_down,
                                                        out, TOT, En, Hn);
}